// round 3
// baseline (speedup 1.0000x reference)
#include <cuda_runtime.h>
#include <math.h>

#define H   16
#define HD  64
#define NQ  2048
#define NKV 4096
#define CD  1024

// ---------------- scratch (device globals: allocation-free) ----------------
__device__ float g_qkv[NQ * 3 * CD];   // 2048 x 3072
__device__ float g_kv [NQ * 2 * CD];   // 2048 x 2048
__device__ float g_q  [H * NQ  * HD];  // [h][n][d]
__device__ float g_k  [H * NKV * HD];  // [h][n][d]  (0..2047 = kx w/ rope, 2048.. = ky)
__device__ float g_v  [H * NKV * HD];
__device__ float g_o  [NQ * CD];       // [n][h*64+d]

// ---------------- SGEMM  C[M,N] = A[M,K] @ B[N,K]^T (+bias) ----------------
// BM=BN=128, BK=8, 256 threads, 8x8 microtile.
__global__ __launch_bounds__(256) void sgemm_nt(
    const float* __restrict__ A, const float* __restrict__ B,
    float* __restrict__ Cp, const float* __restrict__ bias,
    int M, int N, int K)
{
    __shared__ float As[8][128];
    __shared__ float Bs[8][128];
    const int tid = threadIdx.x;
    const int ty = tid >> 4, tx = tid & 15;
    const int lrow = tid >> 1;            // 0..127
    const int lk = (tid & 1) << 2;        // 0 or 4
    const float* Ab = A + ((size_t)blockIdx.y * 128 + lrow) * K + lk;
    const float* Bb = B + ((size_t)blockIdx.x * 128 + lrow) * K + lk;
    float acc[8][8] = {};
    for (int kt = 0; kt < K; kt += 8) {
        float4 a4 = *(const float4*)(Ab + kt);
        float4 b4 = *(const float4*)(Bb + kt);
        __syncthreads();
        As[lk+0][lrow] = a4.x; As[lk+1][lrow] = a4.y;
        As[lk+2][lrow] = a4.z; As[lk+3][lrow] = a4.w;
        Bs[lk+0][lrow] = b4.x; Bs[lk+1][lrow] = b4.y;
        Bs[lk+2][lrow] = b4.z; Bs[lk+3][lrow] = b4.w;
        __syncthreads();
        #pragma unroll
        for (int kk = 0; kk < 8; kk++) {
            float a[8], b[8];
            *(float4*)(a)   = *(const float4*)(&As[kk][ty*8]);
            *(float4*)(a+4) = *(const float4*)(&As[kk][ty*8+4]);
            *(float4*)(b)   = *(const float4*)(&Bs[kk][tx*8]);
            *(float4*)(b+4) = *(const float4*)(&Bs[kk][tx*8+4]);
            #pragma unroll
            for (int i = 0; i < 8; i++)
                #pragma unroll
                for (int j = 0; j < 8; j++)
                    acc[i][j] = fmaf(a[i], b[j], acc[i][j]);
        }
    }
    float bj[8];
    #pragma unroll
    for (int j = 0; j < 8; j++)
        bj[j] = bias ? bias[blockIdx.x*128 + tx*8 + j] : 0.f;
    float* Cb = Cp + ((size_t)blockIdx.y*128 + ty*8) * N + blockIdx.x*128 + tx*8;
    #pragma unroll
    for (int i = 0; i < 8; i++) {
        float4 o0 = make_float4(acc[i][0]+bj[0], acc[i][1]+bj[1],
                                acc[i][2]+bj[2], acc[i][3]+bj[3]);
        float4 o1 = make_float4(acc[i][4]+bj[4], acc[i][5]+bj[5],
                                acc[i][6]+bj[6], acc[i][7]+bj[7]);
        *(float4*)(Cb + (size_t)i*N)     = o0;
        *(float4*)(Cb + (size_t)i*N + 4) = o1;
    }
}

// ------------- x path: RMSNorm(q,kx) + RoPE(q,kx), scatter q/k/v -----------
// one warp per (n, h); lane handles pair (2l, 2l+1)
__global__ __launch_bounds__(256) void post_x(
    const float* __restrict__ pos,
    const float* __restrict__ qw, const float* __restrict__ kw)
{
    int wid  = blockIdx.x * 8 + (threadIdx.x >> 5);
    int lane = threadIdx.x & 31;
    int n = wid >> 4;
    int h = wid & 15;
    const float* base = g_qkv + (size_t)n * 3072 + h * 64 + lane * 2;
    float2 q2 = *(const float2*)(base);
    float2 k2 = *(const float2*)(base + 1024);
    float2 v2 = *(const float2*)(base + 2048);
    float sq = q2.x*q2.x + q2.y*q2.y;
    float sk = k2.x*k2.x + k2.y*k2.y;
    #pragma unroll
    for (int off = 16; off > 0; off >>= 1) {
        sq += __shfl_xor_sync(0xffffffffu, sq, off);
        sk += __shfl_xor_sync(0xffffffffu, sk, off);
    }
    float rq = rsqrtf(sq * (1.f/64.f) + 1e-6f);
    float rk = rsqrtf(sk * (1.f/64.f) + 1e-6f);
    float2 wq = *(const float2*)(qw + lane*2);
    float2 wk = *(const float2*)(kw + lane*2);
    float qe = q2.x * rq * wq.x, qo = q2.y * rq * wq.y;
    float ke = k2.x * rk * wk.x, ko = k2.y * rk * wk.y;
    float2 cs = *(const float2*)(pos + (size_t)n*64 + lane*2);  // (cos, sin)
    float2 qr = make_float2(qe*cs.x - qo*cs.y, qe*cs.y + qo*cs.x);
    float2 kr = make_float2(ke*cs.x - ko*cs.y, ke*cs.y + ko*cs.x);
    *(float2*)(g_q + ((size_t)h*NQ  + n)*64 + lane*2) = qr;
    *(float2*)(g_k + ((size_t)h*NKV + n)*64 + lane*2) = kr;
    *(float2*)(g_v + ((size_t)h*NKV + n)*64 + lane*2) = v2;
}

// ------------- y path: RMSNorm(ky) (no rope), scatter k/v at 2048+ ---------
__global__ __launch_bounds__(256) void post_y(const float* __restrict__ kw)
{
    int wid  = blockIdx.x * 8 + (threadIdx.x >> 5);
    int lane = threadIdx.x & 31;
    int m = wid >> 4;
    int h = wid & 15;
    const float* base = g_kv + (size_t)m * 2048 + h * 64 + lane * 2;
    float2 k2 = *(const float2*)(base);
    float2 v2 = *(const float2*)(base + 1024);
    float sk = k2.x*k2.x + k2.y*k2.y;
    #pragma unroll
    for (int off = 16; off > 0; off >>= 1)
        sk += __shfl_xor_sync(0xffffffffu, sk, off);
    float rk = rsqrtf(sk * (1.f/64.f) + 1e-6f);
    float2 wk = *(const float2*)(kw + lane*2);
    float2 kn = make_float2(k2.x * rk * wk.x, k2.y * rk * wk.y);
    *(float2*)(g_k + ((size_t)h*NKV + 2048 + m)*64 + lane*2) = kn;
    *(float2*)(g_v + ((size_t)h*NKV + 2048 + m)*64 + lane*2) = v2;
}

// ---------------- flash attention: block = (head, 64-q tile) ---------------
// 256 threads as 16x16; thread owns 4x4 of the 64x64 S/O tile.
__global__ __launch_bounds__(256) void flash_kernel()
{
    __shared__ float Qs [64*64];   // [d][row], pre-scaled
    __shared__ float KPs[64*64];   // K tile [d][col], then reused for P [row][col]
    __shared__ float Vs [64*64];   // [key][dim]
    const int h  = blockIdx.y;
    const int qt = blockIdx.x;
    const int tid = threadIdx.x;
    const int ty = tid >> 4, tx = tid & 15;
    const int lr = tid >> 2;           // 0..63
    const int lc = (tid & 3) << 4;     // 0,16,32,48

    const float* qg = g_q + ((size_t)h*NQ + qt*64) * 64 + (size_t)lr*64 + lc;
    #pragma unroll
    for (int i = 0; i < 16; i += 4) {
        float4 t = *(const float4*)(qg + i);
        Qs[(lc+i+0)*64 + lr] = t.x * 0.125f;
        Qs[(lc+i+1)*64 + lr] = t.y * 0.125f;
        Qs[(lc+i+2)*64 + lr] = t.z * 0.125f;
        Qs[(lc+i+3)*64 + lr] = t.w * 0.125f;
    }

    float acc[4][4] = {};
    float mrow[4] = {-INFINITY, -INFINITY, -INFINITY, -INFINITY};
    float lrow[4] = {};
    const float* kg = g_k + (size_t)h*NKV*64 + (size_t)lr*64 + lc;
    const float* vg = g_v + (size_t)h*NKV*64 + (size_t)lr*64 + lc;

    for (int kt = 0; kt < NKV; kt += 64) {
        __syncthreads();   // prior iter done reading KPs(P)/Vs; orders Qs first time
        #pragma unroll
        for (int i = 0; i < 16; i += 4) {
            float4 t = *(const float4*)(kg + (size_t)kt*64 + i);
            KPs[(lc+i+0)*64 + lr] = t.x;
            KPs[(lc+i+1)*64 + lr] = t.y;
            KPs[(lc+i+2)*64 + lr] = t.z;
            KPs[(lc+i+3)*64 + lr] = t.w;
            float4 tv = *(const float4*)(vg + (size_t)kt*64 + i);
            *(float4*)(&Vs[lr*64 + lc + i]) = tv;
        }
        __syncthreads();

        // S = (Q*scale) @ K^T  (64x64)
        float s[4][4] = {};
        #pragma unroll
        for (int d = 0; d < 64; d++) {
            float4 qv = *(const float4*)(&Qs [d*64 + ty*4]);
            float4 kv = *(const float4*)(&KPs[d*64 + tx*4]);
            s[0][0]=fmaf(qv.x,kv.x,s[0][0]); s[0][1]=fmaf(qv.x,kv.y,s[0][1]);
            s[0][2]=fmaf(qv.x,kv.z,s[0][2]); s[0][3]=fmaf(qv.x,kv.w,s[0][3]);
            s[1][0]=fmaf(qv.y,kv.x,s[1][0]); s[1][1]=fmaf(qv.y,kv.y,s[1][1]);
            s[1][2]=fmaf(qv.y,kv.z,s[1][2]); s[1][3]=fmaf(qv.y,kv.w,s[1][3]);
            s[2][0]=fmaf(qv.z,kv.x,s[2][0]); s[2][1]=fmaf(qv.z,kv.y,s[2][1]);
            s[2][2]=fmaf(qv.z,kv.z,s[2][2]); s[2][3]=fmaf(qv.z,kv.w,s[2][3]);
            s[3][0]=fmaf(qv.w,kv.x,s[3][0]); s[3][1]=fmaf(qv.w,kv.y,s[3][1]);
            s[3][2]=fmaf(qv.w,kv.z,s[3][2]); s[3][3]=fmaf(qv.w,kv.w,s[3][3]);
        }

        // online softmax per row (row stats replicated across the 16-lane group)
        #pragma unroll
        for (int i = 0; i < 4; i++) {
            float mx = fmaxf(fmaxf(s[i][0], s[i][1]), fmaxf(s[i][2], s[i][3]));
            #pragma unroll
            for (int off = 8; off > 0; off >>= 1)
                mx = fmaxf(mx, __shfl_xor_sync(0xffffffffu, mx, off, 16));
            float mn = fmaxf(mrow[i], mx);
            float alpha = __expf(mrow[i] - mn);
            mrow[i] = mn;
            float ls = 0.f;
            #pragma unroll
            for (int j = 0; j < 4; j++) { s[i][j] = __expf(s[i][j] - mn); ls += s[i][j]; }
            #pragma unroll
            for (int off = 8; off > 0; off >>= 1)
                ls += __shfl_xor_sync(0xffffffffu, ls, off, 16);
            lrow[i] = lrow[i] * alpha + ls;
            acc[i][0] *= alpha; acc[i][1] *= alpha;
            acc[i][2] *= alpha; acc[i][3] *= alpha;
        }

        __syncthreads();   // everyone done reading K from KPs
        #pragma unroll
        for (int i = 0; i < 4; i++)
            *(float4*)(&KPs[(ty*4+i)*64 + tx*4]) =
                make_float4(s[i][0], s[i][1], s[i][2], s[i][3]);
        __syncthreads();

        // O += P @ V
        #pragma unroll
        for (int cc = 0; cc < 64; cc++) {
            float4 vv = *(const float4*)(&Vs[cc*64 + tx*4]);
            float p0 = KPs[(ty*4+0)*64 + cc];
            float p1 = KPs[(ty*4+1)*64 + cc];
            float p2 = KPs[(ty*4+2)*64 + cc];
            float p3 = KPs[(ty*4+3)*64 + cc];
            acc[0][0]=fmaf(p0,vv.x,acc[0][0]); acc[0][1]=fmaf(p0,vv.y,acc[0][1]);
            acc[0][2]=fmaf(p0,vv.z,acc[0][2]); acc[0][3]=fmaf(p0,vv.w,acc[0][3]);
            acc[1][0]=fmaf(p1,vv.x,acc[1][0]); acc[1][1]=fmaf(p1,vv.y,acc[1][1]);
            acc[1][2]=fmaf(p1,vv.z,acc[1][2]); acc[1][3]=fmaf(p1,vv.w,acc[1][3]);
            acc[2][0]=fmaf(p2,vv.x,acc[2][0]); acc[2][1]=fmaf(p2,vv.y,acc[2][1]);
            acc[2][2]=fmaf(p2,vv.z,acc[2][2]); acc[2][3]=fmaf(p2,vv.w,acc[2][3]);
            acc[3][0]=fmaf(p3,vv.x,acc[3][0]); acc[3][1]=fmaf(p3,vv.y,acc[3][1]);
            acc[3][2]=fmaf(p3,vv.z,acc[3][2]); acc[3][3]=fmaf(p3,vv.w,acc[3][3]);
        }
    }

    #pragma unroll
    for (int i = 0; i < 4; i++) {
        float inv = 1.f / lrow[i];
        float4 r = make_float4(acc[i][0]*inv, acc[i][1]*inv,
                               acc[i][2]*inv, acc[i][3]*inv);
        *(float4*)(g_o + (size_t)(qt*64 + ty*4 + i) * CD + h*64 + tx*4) = r;
    }
}

// --------------------------------- launch ----------------------------------
extern "C" void kernel_launch(void* const* d_in, const int* in_sizes, int n_in,
                              void* d_out, int out_size)
{
    (void)in_sizes; (void)n_in; (void)out_size;
    const float* x      = (const float*)d_in[0];
    const float* y      = (const float*)d_in[1];
    const float* pos    = (const float*)d_in[2];
    const float* w_qkv  = (const float*)d_in[3];
    const float* w_kv   = (const float*)d_in[4];
    const float* w_proj = (const float*)d_in[5];
    const float* b_proj = (const float*)d_in[6];
    const float* qw     = (const float*)d_in[7];
    const float* kw     = (const float*)d_in[8];
    float* out = (float*)d_out;

    float *qkv, *kv, *ob;
    cudaGetSymbolAddress((void**)&qkv, g_qkv);
    cudaGetSymbolAddress((void**)&kv,  g_kv);
    cudaGetSymbolAddress((void**)&ob,  g_o);

    // qkv = x @ Wqkv^T   (2048 x 3072)
    sgemm_nt<<<dim3(3072/128, 2048/128), 256>>>(x, w_qkv, qkv, nullptr, 2048, 3072, 1024);
    // kv  = y @ Wkv^T    (2048 x 2048)
    sgemm_nt<<<dim3(2048/128, 2048/128), 256>>>(y, w_kv, kv, nullptr, 2048, 2048, 1024);
    // norms + rope + scatter to [h][seq][d]
    post_x<<<4096, 256>>>(pos, qw, kw);
    post_y<<<4096, 256>>>(kw);
    // attention -> g_o [n][C]
    flash_kernel<<<dim3(NQ/64, H), 256>>>();
    // out = o @ Wproj^T + b
    sgemm_nt<<<dim3(1024/128, 2048/128), 256>>>(ob, w_proj, out, b_proj, 2048, 1024, 1024);
}

// round 6
// speedup vs baseline: 1.0199x; 1.0199x over previous
#include <cuda_runtime.h>
#include <math.h>

#define H   16
#define HD  64
#define NQ  2048
#define NKV 4096
#define CD  1024

typedef unsigned long long u64;

// ---------------- packed f32x2 helpers (Blackwell FFMA2 path) ----------------
__device__ __forceinline__ u64 pack_dup(float x) {
    u64 r; unsigned xi = __float_as_uint(x);
    asm("mov.b64 %0, {%1, %1};" : "=l"(r) : "r"(xi));
    return r;
}
__device__ __forceinline__ void fma2(u64& d, u64 a, u64 b) {
    asm("fma.rn.f32x2 %0, %1, %2, %0;" : "+l"(d) : "l"(a), "l"(b));
}
__device__ __forceinline__ void mul2ip(u64& d, u64 a) {  // d = d * a
    asm("mul.rn.f32x2 %0, %0, %1;" : "+l"(d) : "l"(a));
}
__device__ __forceinline__ float2 unpack2(u64 v) {
    unsigned lo, hi;
    asm("mov.b64 {%0, %1}, %2;" : "=r"(lo), "=r"(hi) : "l"(v));
    return make_float2(__uint_as_float(lo), __uint_as_float(hi));
}

// ---------------- scratch (device globals: allocation-free) ----------------
__device__ float g_qkv[NQ * 3 * CD];   // 2048 x 3072
__device__ float g_kv [NQ * 2 * CD];   // 2048 x 2048
__device__ float g_q  [H * NQ  * HD];  // [h][n][d]
__device__ float g_k  [H * NKV * HD];  // [h][n][d]  (0..2047 = kx w/ rope, 2048.. = ky)
__device__ float g_v  [H * NKV * HD];
__device__ float g_o  [NQ * CD];       // [n][h*64+d]

// ---------------- SGEMM  C[M,N] = A[M,K] @ B[N,K]^T (+bias) ----------------
// BM=BN=128, BK=8, 256 threads, 8x8 microtile, FFMA2 inner product.
__global__ __launch_bounds__(256) void sgemm_nt(
    const float* __restrict__ A, const float* __restrict__ B,
    float* __restrict__ Cp, const float* __restrict__ bias,
    int M, int N, int K)
{
    __shared__ float As[8][128];
    __shared__ float Bs[8][128];
    const int tid = threadIdx.x;
    const int ty = tid >> 4, tx = tid & 15;
    const int lrow = tid >> 1;            // 0..127
    const int lk = (tid & 1) << 2;        // 0 or 4
    const float* Ab = A + ((size_t)blockIdx.y * 128 + lrow) * K + lk;
    const float* Bb = B + ((size_t)blockIdx.x * 128 + lrow) * K + lk;
    u64 acc2[8][4] = {};                  // 8 rows x 4 col-pairs
    for (int kt = 0; kt < K; kt += 8) {
        float4 a4 = *(const float4*)(Ab + kt);
        float4 b4 = *(const float4*)(Bb + kt);
        __syncthreads();
        As[lk+0][lrow] = a4.x; As[lk+1][lrow] = a4.y;
        As[lk+2][lrow] = a4.z; As[lk+3][lrow] = a4.w;
        Bs[lk+0][lrow] = b4.x; Bs[lk+1][lrow] = b4.y;
        Bs[lk+2][lrow] = b4.z; Bs[lk+3][lrow] = b4.w;
        __syncthreads();
        #pragma unroll
        for (int kk = 0; kk < 8; kk++) {
            float4 a0 = *(const float4*)(&As[kk][ty*8]);
            float4 a1 = *(const float4*)(&As[kk][ty*8+4]);
            ulonglong2 bp0 = *(const ulonglong2*)(&Bs[kk][tx*8]);     // pairs (b0,b1),(b2,b3)
            ulonglong2 bp1 = *(const ulonglong2*)(&Bs[kk][tx*8+4]);   // pairs (b4,b5),(b6,b7)
            u64 ad[8];
            ad[0]=pack_dup(a0.x); ad[1]=pack_dup(a0.y);
            ad[2]=pack_dup(a0.z); ad[3]=pack_dup(a0.w);
            ad[4]=pack_dup(a1.x); ad[5]=pack_dup(a1.y);
            ad[6]=pack_dup(a1.z); ad[7]=pack_dup(a1.w);
            #pragma unroll
            for (int i = 0; i < 8; i++) {
                fma2(acc2[i][0], ad[i], bp0.x);
                fma2(acc2[i][1], ad[i], bp0.y);
                fma2(acc2[i][2], ad[i], bp1.x);
                fma2(acc2[i][3], ad[i], bp1.y);
            }
        }
    }
    float bj[8];
    #pragma unroll
    for (int j = 0; j < 8; j++)
        bj[j] = bias ? bias[blockIdx.x*128 + tx*8 + j] : 0.f;
    float* Cb = Cp + ((size_t)blockIdx.y*128 + ty*8) * N + blockIdx.x*128 + tx*8;
    #pragma unroll
    for (int i = 0; i < 8; i++) {
        float2 c0 = unpack2(acc2[i][0]);
        float2 c1 = unpack2(acc2[i][1]);
        float2 c2 = unpack2(acc2[i][2]);
        float2 c3 = unpack2(acc2[i][3]);
        float4 o0 = make_float4(c0.x+bj[0], c0.y+bj[1], c1.x+bj[2], c1.y+bj[3]);
        float4 o1 = make_float4(c2.x+bj[4], c2.y+bj[5], c3.x+bj[6], c3.y+bj[7]);
        *(float4*)(Cb + (size_t)i*N)     = o0;
        *(float4*)(Cb + (size_t)i*N + 4) = o1;
    }
}

// ------------- x path: RMSNorm(q,kx) + RoPE(q,kx), scatter q/k/v -----------
__global__ __launch_bounds__(256) void post_x(
    const float* __restrict__ pos,
    const float* __restrict__ qw, const float* __restrict__ kw)
{
    int wid  = blockIdx.x * 8 + (threadIdx.x >> 5);
    int lane = threadIdx.x & 31;
    int n = wid >> 4;
    int h = wid & 15;
    const float* base = g_qkv + (size_t)n * 3072 + h * 64 + lane * 2;
    float2 q2 = *(const float2*)(base);
    float2 k2 = *(const float2*)(base + 1024);
    float2 v2 = *(const float2*)(base + 2048);
    float sq = q2.x*q2.x + q2.y*q2.y;
    float sk = k2.x*k2.x + k2.y*k2.y;
    #pragma unroll
    for (int off = 16; off > 0; off >>= 1) {
        sq += __shfl_xor_sync(0xffffffffu, sq, off);
        sk += __shfl_xor_sync(0xffffffffu, sk, off);
    }
    float rq = rsqrtf(sq * (1.f/64.f) + 1e-6f);
    float rk = rsqrtf(sk * (1.f/64.f) + 1e-6f);
    float2 wq = *(const float2*)(qw + lane*2);
    float2 wk = *(const float2*)(kw + lane*2);
    float qe = q2.x * rq * wq.x, qo = q2.y * rq * wq.y;
    float ke = k2.x * rk * wk.x, ko = k2.y * rk * wk.y;
    float2 cs = *(const float2*)(pos + (size_t)n*64 + lane*2);  // (cos, sin)
    float2 qr = make_float2(qe*cs.x - qo*cs.y, qe*cs.y + qo*cs.x);
    float2 kr = make_float2(ke*cs.x - ko*cs.y, ke*cs.y + ko*cs.x);
    *(float2*)(g_q + ((size_t)h*NQ  + n)*64 + lane*2) = qr;
    *(float2*)(g_k + ((size_t)h*NKV + n)*64 + lane*2) = kr;
    *(float2*)(g_v + ((size_t)h*NKV + n)*64 + lane*2) = v2;
}

// ------------- y path: RMSNorm(ky) (no rope), scatter k/v at 2048+ ---------
__global__ __launch_bounds__(256) void post_y(const float* __restrict__ kw)
{
    int wid  = blockIdx.x * 8 + (threadIdx.x >> 5);
    int lane = threadIdx.x & 31;
    int m = wid >> 4;
    int h = wid & 15;
    const float* base = g_kv + (size_t)m * 2048 + h * 64 + lane * 2;
    float2 k2 = *(const float2*)(base);
    float2 v2 = *(const float2*)(base + 1024);
    float sk = k2.x*k2.x + k2.y*k2.y;
    #pragma unroll
    for (int off = 16; off > 0; off >>= 1)
        sk += __shfl_xor_sync(0xffffffffu, sk, off);
    float rk = rsqrtf(sk * (1.f/64.f) + 1e-6f);
    float2 wk = *(const float2*)(kw + lane*2);
    float2 kn = make_float2(k2.x * rk * wk.x, k2.y * rk * wk.y);
    *(float2*)(g_k + ((size_t)h*NKV + 2048 + m)*64 + lane*2) = kn;
    *(float2*)(g_v + ((size_t)h*NKV + 2048 + m)*64 + lane*2) = v2;
}

// ---------------- flash attention: block = (head, 64-q tile) ---------------
// 256 threads as 16x16; thread owns 4x4 of the 64x64 S/O tile. FFMA2 GEMMs.
__global__ __launch_bounds__(256) void flash_kernel()
{
    __shared__ float Qs [64*64];   // [d][row], pre-scaled
    __shared__ float KPs[64*64];   // K tile [d][col], then reused for P [row][col]
    __shared__ float Vs [64*64];   // [key][dim]
    const int h  = blockIdx.y;
    const int qt = blockIdx.x;
    const int tid = threadIdx.x;
    const int ty = tid >> 4, tx = tid & 15;
    const int lr = tid >> 2;           // 0..63
    const int lc = (tid & 3) << 4;     // 0,16,32,48

    const float* qg = g_q + ((size_t)h*NQ + qt*64) * 64 + (size_t)lr*64 + lc;
    #pragma unroll
    for (int i = 0; i < 16; i += 4) {
        float4 t = *(const float4*)(qg + i);
        Qs[(lc+i+0)*64 + lr] = t.x * 0.125f;
        Qs[(lc+i+1)*64 + lr] = t.y * 0.125f;
        Qs[(lc+i+2)*64 + lr] = t.z * 0.125f;
        Qs[(lc+i+3)*64 + lr] = t.w * 0.125f;
    }

    u64 acc2[4][2] = {};               // 4 rows x 2 col-pairs of O
    float mrow[4] = {-INFINITY, -INFINITY, -INFINITY, -INFINITY};
    float lrow[4] = {};
    const float* kg = g_k + (size_t)h*NKV*64 + (size_t)lr*64 + lc;
    const float* vg = g_v + (size_t)h*NKV*64 + (size_t)lr*64 + lc;

    for (int kt = 0; kt < NKV; kt += 64) {
        __syncthreads();   // prior iter done reading KPs(P)/Vs; orders Qs first time
        #pragma unroll
        for (int i = 0; i < 16; i += 4) {
            float4 t = *(const float4*)(kg + (size_t)kt*64 + i);
            KPs[(lc+i+0)*64 + lr] = t.x;
            KPs[(lc+i+1)*64 + lr] = t.y;
            KPs[(lc+i+2)*64 + lr] = t.z;
            KPs[(lc+i+3)*64 + lr] = t.w;
            float4 tv = *(const float4*)(vg + (size_t)kt*64 + i);
            *(float4*)(&Vs[lr*64 + lc + i]) = tv;
        }
        __syncthreads();

        // S = (Q*scale) @ K^T  (64x64), packed pairs along key dim
        u64 s2[4][2] = {};
        #pragma unroll
        for (int d = 0; d < 64; d++) {
            float4 qv = *(const float4*)(&Qs [d*64 + ty*4]);
            ulonglong2 kp = *(const ulonglong2*)(&KPs[d*64 + tx*4]);  // (k0,k1),(k2,k3)
            u64 q0 = pack_dup(qv.x), q1 = pack_dup(qv.y);
            u64 q2 = pack_dup(qv.z), q3 = pack_dup(qv.w);
            fma2(s2[0][0], q0, kp.x); fma2(s2[0][1], q0, kp.y);
            fma2(s2[1][0], q1, kp.x); fma2(s2[1][1], q1, kp.y);
            fma2(s2[2][0], q2, kp.x); fma2(s2[2][1], q2, kp.y);
            fma2(s2[3][0], q3, kp.x); fma2(s2[3][1], q3, kp.y);
        }
        float s[4][4];
        #pragma unroll
        for (int i = 0; i < 4; i++) {
            float2 p0 = unpack2(s2[i][0]);
            float2 p1 = unpack2(s2[i][1]);
            s[i][0] = p0.x; s[i][1] = p0.y; s[i][2] = p1.x; s[i][3] = p1.y;
        }

        // online softmax per row (row stats replicated across the 16-lane group)
        #pragma unroll
        for (int i = 0; i < 4; i++) {
            float mx = fmaxf(fmaxf(s[i][0], s[i][1]), fmaxf(s[i][2], s[i][3]));
            #pragma unroll
            for (int off = 8; off > 0; off >>= 1)
                mx = fmaxf(mx, __shfl_xor_sync(0xffffffffu, mx, off, 16));
            float mn = fmaxf(mrow[i], mx);
            float alpha = __expf(mrow[i] - mn);
            mrow[i] = mn;
            float ls = 0.f;
            #pragma unroll
            for (int j = 0; j < 4; j++) { s[i][j] = __expf(s[i][j] - mn); ls += s[i][j]; }
            #pragma unroll
            for (int off = 8; off > 0; off >>= 1)
                ls += __shfl_xor_sync(0xffffffffu, ls, off, 16);
            lrow[i] = lrow[i] * alpha + ls;
            u64 ad = pack_dup(alpha);
            mul2ip(acc2[i][0], ad);
            mul2ip(acc2[i][1], ad);
        }

        __syncthreads();   // everyone done reading K from KPs
        #pragma unroll
        for (int i = 0; i < 4; i++)
            *(float4*)(&KPs[(ty*4+i)*64 + tx*4]) =
                make_float4(s[i][0], s[i][1], s[i][2], s[i][3]);
        __syncthreads();

        // O += P @ V, packed pairs along dim
        #pragma unroll
        for (int cc = 0; cc < 64; cc++) {
            ulonglong2 vv = *(const ulonglong2*)(&Vs[cc*64 + tx*4]);  // (v0,v1),(v2,v3)
            u64 p0 = pack_dup(KPs[(ty*4+0)*64 + cc]);
            u64 p1 = pack_dup(KPs[(ty*4+1)*64 + cc]);
            u64 p2 = pack_dup(KPs[(ty*4+2)*64 + cc]);
            u64 p3 = pack_dup(KPs[(ty*4+3)*64 + cc]);
            fma2(acc2[0][0], p0, vv.x); fma2(acc2[0][1], p0, vv.y);
            fma2(acc2[1][0], p1, vv.x); fma2(acc2[1][1], p1, vv.y);
            fma2(acc2[2][0], p2, vv.x); fma2(acc2[2][1], p2, vv.y);
            fma2(acc2[3][0], p3, vv.x); fma2(acc2[3][1], p3, vv.y);
        }
    }

    #pragma unroll
    for (int i = 0; i < 4; i++) {
        float inv = 1.f / lrow[i];
        float2 a0 = unpack2(acc2[i][0]);
        float2 a1 = unpack2(acc2[i][1]);
        float4 r = make_float4(a0.x*inv, a0.y*inv, a1.x*inv, a1.y*inv);
        *(float4*)(g_o + (size_t)(qt*64 + ty*4 + i) * CD + h*64 + tx*4) = r;
    }
}

// --------------------------------- launch ----------------------------------
extern "C" void kernel_launch(void* const* d_in, const int* in_sizes, int n_in,
                              void* d_out, int out_size)
{
    (void)in_sizes; (void)n_in; (void)out_size;
    const float* x      = (const float*)d_in[0];
    const float* y      = (const float*)d_in[1];
    const float* pos    = (const float*)d_in[2];
    const float* w_qkv  = (const float*)d_in[3];
    const float* w_kv   = (const float*)d_in[4];
    const float* w_proj = (const float*)d_in[5];
    const float* b_proj = (const float*)d_in[6];
    const float* qw     = (const float*)d_in[7];
    const float* kw     = (const float*)d_in[8];
    float* out = (float*)d_out;

    float *qkv, *kv, *ob;
    cudaGetSymbolAddress((void**)&qkv, g_qkv);
    cudaGetSymbolAddress((void**)&kv,  g_kv);
    cudaGetSymbolAddress((void**)&ob,  g_o);

    // qkv = x @ Wqkv^T   (2048 x 3072)
    sgemm_nt<<<dim3(3072/128, 2048/128), 256>>>(x, w_qkv, qkv, nullptr, 2048, 3072, 1024);
    // kv  = y @ Wkv^T    (2048 x 2048)
    sgemm_nt<<<dim3(2048/128, 2048/128), 256>>>(y, w_kv, kv, nullptr, 2048, 2048, 1024);
    // norms + rope + scatter to [h][seq][d]
    post_x<<<4096, 256>>>(pos, qw, kw);
    post_y<<<4096, 256>>>(kw);
    // attention -> g_o [n][C]
    flash_kernel<<<dim3(NQ/64, H), 256>>>();
    // out = o @ Wproj^T + b
    sgemm_nt<<<dim3(1024/128, 2048/128), 256>>>(ob, w_proj, out, b_proj, 2048, 1024, 1024);
}

// round 11
// speedup vs baseline: 1.2694x; 1.2447x over previous
#include <cuda_runtime.h>
#include <cuda_bf16.h>
#include <math.h>
#include <stdint.h>

#define H   16
#define HD  64
#define NQ  2048
#define NKV 4096
#define CD  1024
#define KDIM 1024

typedef unsigned long long u64;
typedef unsigned int u32;

// ---------------- packed f32x2 helpers (flash kernel) ----------------
__device__ __forceinline__ u64 pack_dup(float x) {
    u64 r; unsigned xi = __float_as_uint(x);
    asm("mov.b64 %0, {%1, %1};" : "=l"(r) : "r"(xi));
    return r;
}
__device__ __forceinline__ void fma2(u64& d, u64 a, u64 b) {
    asm("fma.rn.f32x2 %0, %1, %2, %0;" : "+l"(d) : "l"(a), "l"(b));
}
__device__ __forceinline__ void mul2ip(u64& d, u64 a) {
    asm("mul.rn.f32x2 %0, %0, %1;" : "+l"(d) : "l"(a));
}
__device__ __forceinline__ float2 unpack2(u64 v) {
    unsigned lo, hi;
    asm("mov.b64 {%0, %1}, %2;" : "=r"(lo), "=r"(hi) : "l"(v));
    return make_float2(__uint_as_float(lo), __uint_as_float(hi));
}

// ---------------- scratch (device globals: allocation-free) ----------------
__device__ __align__(16) float g_qkv[NQ * 3 * CD];
__device__ __align__(16) float g_kv [NQ * 2 * CD];
__device__ __align__(16) float g_q  [H * NQ  * HD];
__device__ __align__(16) float g_k  [H * NKV * HD];
__device__ __align__(16) float g_v  [H * NKV * HD];
__device__ __align__(16) float g_o  [NQ * CD];

// bf16 split operand buffers
__device__ __align__(16) __nv_bfloat16 g_xh[NQ*CD],  g_xl[NQ*CD];    // x, reused for o
__device__ __align__(16) __nv_bfloat16 g_yh[NQ*CD],  g_yl[NQ*CD];
__device__ __align__(16) __nv_bfloat16 g_wqh[3*CD*CD], g_wql[3*CD*CD];
__device__ __align__(16) __nv_bfloat16 g_wkh[2*CD*CD], g_wkl[2*CD*CD];
__device__ __align__(16) __nv_bfloat16 g_wph[CD*CD],   g_wpl[CD*CD];

// ---------------- split: fp32 -> bf16 hi + bf16 lo -------------------------
__global__ __launch_bounds__(256) void split_kernel(
    const float* __restrict__ src, __nv_bfloat16* __restrict__ hi,
    __nv_bfloat16* __restrict__ lo, int n4)
{
    int i = blockIdx.x * 256 + threadIdx.x;
    if (i >= n4) return;
    float4 v = ((const float4*)src)[i];
    __nv_bfloat16 h0 = __float2bfloat16_rn(v.x);
    __nv_bfloat16 h1 = __float2bfloat16_rn(v.y);
    __nv_bfloat16 h2 = __float2bfloat16_rn(v.z);
    __nv_bfloat16 h3 = __float2bfloat16_rn(v.w);
    __nv_bfloat16 l0 = __float2bfloat16_rn(v.x - __bfloat162float(h0));
    __nv_bfloat16 l1 = __float2bfloat16_rn(v.y - __bfloat162float(h1));
    __nv_bfloat16 l2 = __float2bfloat16_rn(v.z - __bfloat162float(h2));
    __nv_bfloat16 l3 = __float2bfloat16_rn(v.w - __bfloat162float(h3));
    __nv_bfloat162* hp = (__nv_bfloat162*)(hi + (size_t)i*4);
    __nv_bfloat162* lp = (__nv_bfloat162*)(lo + (size_t)i*4);
    hp[0] = __nv_bfloat162(h0, h1); hp[1] = __nv_bfloat162(h2, h3);
    lp[0] = __nv_bfloat162(l0, l1); lp[1] = __nv_bfloat162(l2, l3);
}

// ============ bf16-split tensor-core GEMM: C[M,N] = A @ B^T (+bias) ========
// 128x128 tile, BK=32, 256 threads (8 warps, 4M x 2N), mma.sync m16n8k16.
// SA=40 bf16 (80B row stride): every uint4 slot 16B-aligned, frag LDS
// conflict-free (bank = (row*20 + tq) mod 32 covers all 32 banks).
#define SA 40

__device__ __forceinline__ void mma_bf16(float* c, const u32* a, const u32* b) {
    asm volatile(
        "mma.sync.aligned.m16n8k16.row.col.f32.bf16.bf16.f32 "
        "{%0,%1,%2,%3}, {%4,%5,%6,%7}, {%8,%9}, {%0,%1,%2,%3};"
        : "+f"(c[0]), "+f"(c[1]), "+f"(c[2]), "+f"(c[3])
        : "r"(a[0]), "r"(a[1]), "r"(a[2]), "r"(a[3]), "r"(b[0]), "r"(b[1]));
}

__global__ __launch_bounds__(256, 2) void gemm_bf16(
    const __nv_bfloat16* __restrict__ Ah, const __nv_bfloat16* __restrict__ Al,
    const __nv_bfloat16* __restrict__ Bh, const __nv_bfloat16* __restrict__ Bl,
    float* __restrict__ Cp, const float* __restrict__ bias, int N)
{
    __shared__ __align__(16) __nv_bfloat16 sAh[128*SA], sAl[128*SA];
    __shared__ __align__(16) __nv_bfloat16 sBh[128*SA], sBl[128*SA];

    const int tid = threadIdx.x;
    const int wid = tid >> 5, lane = tid & 31;
    const int wm = wid & 3, wn = wid >> 2;        // warp tile: 32M x 64N
    const int grp = lane >> 2, tq = lane & 3;
    const int bm = blockIdx.y * 128, bn = blockIdx.x * 128;

    float acc[2][8][4] = {};                      // [m-tile][n-tile][frag]

    for (int kt = 0; kt < KDIM; kt += 32) {
        __syncthreads();
        // load 128x32 bf16 of each of 4 arrays; chunk = 8 bf16 (16B)
        #pragma unroll
        for (int i = 0; i < 2; i++) {
            int c = tid + i*256;                  // 0..511
            int row = c >> 2, kc = c & 3;
            size_t goA = (size_t)(bm + row) * KDIM + kt + kc*8;
            size_t goB = (size_t)(bn + row) * KDIM + kt + kc*8;
            int so = row * SA + kc * 8;
            *(uint4*)&sAh[so] = *(const uint4*)(Ah + goA);
            *(uint4*)&sAl[so] = *(const uint4*)(Al + goA);
            *(uint4*)&sBh[so] = *(const uint4*)(Bh + goB);
            *(uint4*)&sBl[so] = *(const uint4*)(Bl + goB);
        }
        __syncthreads();

        #pragma unroll
        for (int ks = 0; ks < 32; ks += 16) {
            u32 ah[8], al[8];
            #pragma unroll
            for (int mt = 0; mt < 2; mt++) {
                int r0 = (wm*32 + mt*16 + grp) * SA + ks + 2*tq;
                int r1 = r0 + 8*SA;
                ah[mt*4+0] = *(const u32*)&sAh[r0];
                ah[mt*4+1] = *(const u32*)&sAh[r1];
                ah[mt*4+2] = *(const u32*)&sAh[r0 + 8];
                ah[mt*4+3] = *(const u32*)&sAh[r1 + 8];
                al[mt*4+0] = *(const u32*)&sAl[r0];
                al[mt*4+1] = *(const u32*)&sAl[r1];
                al[mt*4+2] = *(const u32*)&sAl[r0 + 8];
                al[mt*4+3] = *(const u32*)&sAl[r1 + 8];
            }
            #pragma unroll
            for (int nt = 0; nt < 8; nt++) {
                int b0 = (wn*64 + nt*8 + grp) * SA + ks + 2*tq;
                u32 bh[2], bl[2];
                bh[0] = *(const u32*)&sBh[b0];
                bh[1] = *(const u32*)&sBh[b0 + 8];
                bl[0] = *(const u32*)&sBl[b0];
                bl[1] = *(const u32*)&sBl[b0 + 8];
                mma_bf16(acc[0][nt], ah,   bh);   // Ah*Bh
                mma_bf16(acc[1][nt], ah+4, bh);
                mma_bf16(acc[0][nt], ah,   bl);   // Ah*Bl
                mma_bf16(acc[1][nt], ah+4, bl);
                mma_bf16(acc[0][nt], al,   bh);   // Al*Bh
                mma_bf16(acc[1][nt], al+4, bh);
            }
        }
    }

    // epilogue
    #pragma unroll
    for (int mt = 0; mt < 2; mt++) {
        int row0 = bm + wm*32 + mt*16 + grp;
        #pragma unroll
        for (int nt = 0; nt < 8; nt++) {
            int col = bn + wn*64 + nt*8 + 2*tq;
            float b0 = 0.f, b1 = 0.f;
            if (bias) { b0 = bias[col]; b1 = bias[col+1]; }
            float2 v0 = make_float2(acc[mt][nt][0] + b0, acc[mt][nt][1] + b1);
            float2 v1 = make_float2(acc[mt][nt][2] + b0, acc[mt][nt][3] + b1);
            *(float2*)(Cp + (size_t)row0       * N + col) = v0;
            *(float2*)(Cp + (size_t)(row0 + 8) * N + col) = v1;
        }
    }
}

// ------------- x path: RMSNorm(q,kx) + RoPE(q,kx), scatter q/k/v -----------
__global__ __launch_bounds__(256) void post_x(
    const float* __restrict__ pos,
    const float* __restrict__ qw, const float* __restrict__ kw)
{
    int wid  = blockIdx.x * 8 + (threadIdx.x >> 5);
    int lane = threadIdx.x & 31;
    int n = wid >> 4;
    int h = wid & 15;
    const float* base = g_qkv + (size_t)n * 3072 + h * 64 + lane * 2;
    float2 q2 = *(const float2*)(base);
    float2 k2 = *(const float2*)(base + 1024);
    float2 v2 = *(const float2*)(base + 2048);
    float sq = q2.x*q2.x + q2.y*q2.y;
    float sk = k2.x*k2.x + k2.y*k2.y;
    #pragma unroll
    for (int off = 16; off > 0; off >>= 1) {
        sq += __shfl_xor_sync(0xffffffffu, sq, off);
        sk += __shfl_xor_sync(0xffffffffu, sk, off);
    }
    float rq = rsqrtf(sq * (1.f/64.f) + 1e-6f);
    float rk = rsqrtf(sk * (1.f/64.f) + 1e-6f);
    float2 wq = *(const float2*)(qw + lane*2);
    float2 wk = *(const float2*)(kw + lane*2);
    float qe = q2.x * rq * wq.x, qo = q2.y * rq * wq.y;
    float ke = k2.x * rk * wk.x, ko = k2.y * rk * wk.y;
    float2 cs = *(const float2*)(pos + (size_t)n*64 + lane*2);
    float2 qr = make_float2(qe*cs.x - qo*cs.y, qe*cs.y + qo*cs.x);
    float2 kr = make_float2(ke*cs.x - ko*cs.y, ke*cs.y + ko*cs.x);
    *(float2*)(g_q + ((size_t)h*NQ  + n)*64 + lane*2) = qr;
    *(float2*)(g_k + ((size_t)h*NKV + n)*64 + lane*2) = kr;
    *(float2*)(g_v + ((size_t)h*NKV + n)*64 + lane*2) = v2;
}

// ------------- y path: RMSNorm(ky) (no rope), scatter k/v at 2048+ ---------
__global__ __launch_bounds__(256) void post_y(const float* __restrict__ kw)
{
    int wid  = blockIdx.x * 8 + (threadIdx.x >> 5);
    int lane = threadIdx.x & 31;
    int m = wid >> 4;
    int h = wid & 15;
    const float* base = g_kv + (size_t)m * 2048 + h * 64 + lane * 2;
    float2 k2 = *(const float2*)(base);
    float2 v2 = *(const float2*)(base + 1024);
    float sk = k2.x*k2.x + k2.y*k2.y;
    #pragma unroll
    for (int off = 16; off > 0; off >>= 1)
        sk += __shfl_xor_sync(0xffffffffu, sk, off);
    float rk = rsqrtf(sk * (1.f/64.f) + 1e-6f);
    float2 wk = *(const float2*)(kw + lane*2);
    float2 kn = make_float2(k2.x * rk * wk.x, k2.y * rk * wk.y);
    *(float2*)(g_k + ((size_t)h*NKV + 2048 + m)*64 + lane*2) = kn;
    *(float2*)(g_v + ((size_t)h*NKV + 2048 + m)*64 + lane*2) = v2;
}

// ---------------- flash attention: block = (head, 64-q tile) ---------------
__global__ __launch_bounds__(256) void flash_kernel()
{
    __shared__ float Qs [64*64];
    __shared__ float KPs[64*64];
    __shared__ float Vs [64*64];
    const int h  = blockIdx.y;
    const int qt = blockIdx.x;
    const int tid = threadIdx.x;
    const int ty = tid >> 4, tx = tid & 15;
    const int lr = tid >> 2;
    const int lc = (tid & 3) << 4;

    const float* qg = g_q + ((size_t)h*NQ + qt*64) * 64 + (size_t)lr*64 + lc;
    #pragma unroll
    for (int i = 0; i < 16; i += 4) {
        float4 t = *(const float4*)(qg + i);
        Qs[(lc+i+0)*64 + lr] = t.x * 0.125f;
        Qs[(lc+i+1)*64 + lr] = t.y * 0.125f;
        Qs[(lc+i+2)*64 + lr] = t.z * 0.125f;
        Qs[(lc+i+3)*64 + lr] = t.w * 0.125f;
    }

    u64 acc2[4][2] = {};
    float mrow[4] = {-INFINITY, -INFINITY, -INFINITY, -INFINITY};
    float lrow[4] = {};
    const float* kg = g_k + (size_t)h*NKV*64 + (size_t)lr*64 + lc;
    const float* vg = g_v + (size_t)h*NKV*64 + (size_t)lr*64 + lc;

    for (int kt = 0; kt < NKV; kt += 64) {
        __syncthreads();
        #pragma unroll
        for (int i = 0; i < 16; i += 4) {
            float4 t = *(const float4*)(kg + (size_t)kt*64 + i);
            KPs[(lc+i+0)*64 + lr] = t.x;
            KPs[(lc+i+1)*64 + lr] = t.y;
            KPs[(lc+i+2)*64 + lr] = t.z;
            KPs[(lc+i+3)*64 + lr] = t.w;
            float4 tv = *(const float4*)(vg + (size_t)kt*64 + i);
            *(float4*)(&Vs[lr*64 + lc + i]) = tv;
        }
        __syncthreads();

        u64 s2[4][2] = {};
        #pragma unroll
        for (int d = 0; d < 64; d++) {
            float4 qv = *(const float4*)(&Qs [d*64 + ty*4]);
            ulonglong2 kp = *(const ulonglong2*)(&KPs[d*64 + tx*4]);
            u64 q0 = pack_dup(qv.x), q1 = pack_dup(qv.y);
            u64 q2 = pack_dup(qv.z), q3 = pack_dup(qv.w);
            fma2(s2[0][0], q0, kp.x); fma2(s2[0][1], q0, kp.y);
            fma2(s2[1][0], q1, kp.x); fma2(s2[1][1], q1, kp.y);
            fma2(s2[2][0], q2, kp.x); fma2(s2[2][1], q2, kp.y);
            fma2(s2[3][0], q3, kp.x); fma2(s2[3][1], q3, kp.y);
        }
        float s[4][4];
        #pragma unroll
        for (int i = 0; i < 4; i++) {
            float2 p0 = unpack2(s2[i][0]);
            float2 p1 = unpack2(s2[i][1]);
            s[i][0] = p0.x; s[i][1] = p0.y; s[i][2] = p1.x; s[i][3] = p1.y;
        }

        #pragma unroll
        for (int i = 0; i < 4; i++) {
            float mx = fmaxf(fmaxf(s[i][0], s[i][1]), fmaxf(s[i][2], s[i][3]));
            #pragma unroll
            for (int off = 8; off > 0; off >>= 1)
                mx = fmaxf(mx, __shfl_xor_sync(0xffffffffu, mx, off, 16));
            float mn = fmaxf(mrow[i], mx);
            float alpha = __expf(mrow[i] - mn);
            mrow[i] = mn;
            float ls = 0.f;
            #pragma unroll
            for (int j = 0; j < 4; j++) { s[i][j] = __expf(s[i][j] - mn); ls += s[i][j]; }
            #pragma unroll
            for (int off = 8; off > 0; off >>= 1)
                ls += __shfl_xor_sync(0xffffffffu, ls, off, 16);
            lrow[i] = lrow[i] * alpha + ls;
            u64 ad = pack_dup(alpha);
            mul2ip(acc2[i][0], ad);
            mul2ip(acc2[i][1], ad);
        }

        __syncthreads();
        #pragma unroll
        for (int i = 0; i < 4; i++)
            *(float4*)(&KPs[(ty*4+i)*64 + tx*4]) =
                make_float4(s[i][0], s[i][1], s[i][2], s[i][3]);
        __syncthreads();

        #pragma unroll
        for (int cc = 0; cc < 64; cc++) {
            ulonglong2 vv = *(const ulonglong2*)(&Vs[cc*64 + tx*4]);
            u64 p0 = pack_dup(KPs[(ty*4+0)*64 + cc]);
            u64 p1 = pack_dup(KPs[(ty*4+1)*64 + cc]);
            u64 p2 = pack_dup(KPs[(ty*4+2)*64 + cc]);
            u64 p3 = pack_dup(KPs[(ty*4+3)*64 + cc]);
            fma2(acc2[0][0], p0, vv.x); fma2(acc2[0][1], p0, vv.y);
            fma2(acc2[1][0], p1, vv.x); fma2(acc2[1][1], p1, vv.y);
            fma2(acc2[2][0], p2, vv.x); fma2(acc2[2][1], p2, vv.y);
            fma2(acc2[3][0], p3, vv.x); fma2(acc2[3][1], p3, vv.y);
        }
    }

    #pragma unroll
    for (int i = 0; i < 4; i++) {
        float inv = 1.f / lrow[i];
        float2 a0 = unpack2(acc2[i][0]);
        float2 a1 = unpack2(acc2[i][1]);
        float4 r = make_float4(a0.x*inv, a0.y*inv, a1.x*inv, a1.y*inv);
        *(float4*)(g_o + (size_t)(qt*64 + ty*4 + i) * CD + h*64 + tx*4) = r;
    }
}

// --------------------------------- launch ----------------------------------
extern "C" void kernel_launch(void* const* d_in, const int* in_sizes, int n_in,
                              void* d_out, int out_size)
{
    (void)in_sizes; (void)n_in; (void)out_size;
    const float* x      = (const float*)d_in[0];
    const float* y      = (const float*)d_in[1];
    const float* pos    = (const float*)d_in[2];
    const float* w_qkv  = (const float*)d_in[3];
    const float* w_kv   = (const float*)d_in[4];
    const float* w_proj = (const float*)d_in[5];
    const float* b_proj = (const float*)d_in[6];
    const float* qw     = (const float*)d_in[7];
    const float* kw     = (const float*)d_in[8];
    float* out = (float*)d_out;

    float *qkv, *kv, *ob;
    cudaGetSymbolAddress((void**)&qkv, g_qkv);
    cudaGetSymbolAddress((void**)&kv,  g_kv);
    cudaGetSymbolAddress((void**)&ob,  g_o);
    __nv_bfloat16 *xh,*xl,*yh,*yl,*wqh,*wql,*wkh,*wkl,*wph,*wpl;
    cudaGetSymbolAddress((void**)&xh, g_xh);  cudaGetSymbolAddress((void**)&xl, g_xl);
    cudaGetSymbolAddress((void**)&yh, g_yh);  cudaGetSymbolAddress((void**)&yl, g_yl);
    cudaGetSymbolAddress((void**)&wqh, g_wqh); cudaGetSymbolAddress((void**)&wql, g_wql);
    cudaGetSymbolAddress((void**)&wkh, g_wkh); cudaGetSymbolAddress((void**)&wkl, g_wkl);
    cudaGetSymbolAddress((void**)&wph, g_wph); cudaGetSymbolAddress((void**)&wpl, g_wpl);

    // splits (n/4 elements of float4 per thread)
    split_kernel<<<(NQ*CD/4 + 255)/256, 256>>>(x, xh, xl, NQ*CD/4);
    split_kernel<<<(NQ*CD/4 + 255)/256, 256>>>(y, yh, yl, NQ*CD/4);
    split_kernel<<<(3*CD*CD/4 + 255)/256, 256>>>(w_qkv, wqh, wql, 3*CD*CD/4);
    split_kernel<<<(2*CD*CD/4 + 255)/256, 256>>>(w_kv,  wkh, wkl, 2*CD*CD/4);
    split_kernel<<<(CD*CD/4 + 255)/256, 256>>>(w_proj, wph, wpl, CD*CD/4);

    // qkv = x @ Wqkv^T   (2048 x 3072)
    gemm_bf16<<<dim3(3072/128, 2048/128), 256>>>(xh, xl, wqh, wql, qkv, nullptr, 3072);
    // kv  = y @ Wkv^T    (2048 x 2048)
    gemm_bf16<<<dim3(2048/128, 2048/128), 256>>>(yh, yl, wkh, wkl, kv, nullptr, 2048);
    // norms + rope + scatter to [h][seq][d]
    post_x<<<4096, 256>>>(pos, qw, kw);
    post_y<<<4096, 256>>>(kw);
    // attention -> g_o [n][C]
    flash_kernel<<<dim3(NQ/64, H), 256>>>();
    // split o, then out = o @ Wproj^T + b
    split_kernel<<<(NQ*CD/4 + 255)/256, 256>>>(ob, xh, xl, NQ*CD/4);
    gemm_bf16<<<dim3(1024/128, 2048/128), 256>>>(xh, xl, wph, wpl, out, b_proj, 1024);
}

// round 12
// speedup vs baseline: 2.1338x; 1.6809x over previous
#include <cuda_runtime.h>
#include <cuda_bf16.h>
#include <math.h>
#include <stdint.h>

#define H   16
#define HD  64
#define NQ  2048
#define NKV 4096
#define CD  1024
#define KDIM 1024

typedef unsigned long long u64;
typedef unsigned int u32;

// ---------------- scratch (device globals: allocation-free) ----------------
__device__ __align__(16) float g_qkv[NQ * 3 * CD];
__device__ __align__(16) float g_kv [NQ * 2 * CD];
__device__ __align__(16) float g_o  [NQ * CD];

// pre-split bf16 attention operands
__device__ __align__(16) __nv_bfloat16 g_qh[H*NQ*HD],  g_ql[H*NQ*HD];   // [h][n][d], 0.125 baked in
__device__ __align__(16) __nv_bfloat16 g_kh[H*NKV*HD], g_kl[H*NKV*HD];  // [h][key][d]
__device__ __align__(16) __nv_bfloat16 g_vth[H*HD*NKV], g_vtl[H*HD*NKV];// [h][d][key] (transposed)

// bf16 split operand buffers for projection GEMMs
__device__ __align__(16) __nv_bfloat16 g_xh[NQ*CD],  g_xl[NQ*CD];    // x, reused for o
__device__ __align__(16) __nv_bfloat16 g_yh[NQ*CD],  g_yl[NQ*CD];
__device__ __align__(16) __nv_bfloat16 g_wqh[3*CD*CD], g_wql[3*CD*CD];
__device__ __align__(16) __nv_bfloat16 g_wkh[2*CD*CD], g_wkl[2*CD*CD];
__device__ __align__(16) __nv_bfloat16 g_wph[CD*CD],   g_wpl[CD*CD];

// ---------------- helpers --------------------------------------------------
__device__ __forceinline__ void split1(float v, __nv_bfloat16& h, __nv_bfloat16& l) {
    h = __float2bfloat16_rn(v);
    l = __float2bfloat16_rn(v - __bfloat162float(h));
}
// pack {lo, hi} floats into bf16x2 (lo in bits[0:16))
__device__ __forceinline__ u32 packbf2(float lo, float hi) {
    u32 r;
    asm("cvt.rn.bf16x2.f32 %0, %1, %2;" : "=r"(r) : "f"(hi), "f"(lo));
    return r;
}
__device__ __forceinline__ void mma_bf16(float* c, const u32* a, const u32* b) {
    asm volatile(
        "mma.sync.aligned.m16n8k16.row.col.f32.bf16.bf16.f32 "
        "{%0,%1,%2,%3}, {%4,%5,%6,%7}, {%8,%9}, {%0,%1,%2,%3};"
        : "+f"(c[0]), "+f"(c[1]), "+f"(c[2]), "+f"(c[3])
        : "r"(a[0]), "r"(a[1]), "r"(a[2]), "r"(a[3]), "r"(b[0]), "r"(b[1]));
}

// ---------------- split: fp32 -> bf16 hi + bf16 lo -------------------------
__global__ __launch_bounds__(256) void split_kernel(
    const float* __restrict__ src, __nv_bfloat16* __restrict__ hi,
    __nv_bfloat16* __restrict__ lo, int n4)
{
    int i = blockIdx.x * 256 + threadIdx.x;
    if (i >= n4) return;
    float4 v = ((const float4*)src)[i];
    __nv_bfloat16 h0, h1, h2, h3, l0, l1, l2, l3;
    split1(v.x, h0, l0); split1(v.y, h1, l1);
    split1(v.z, h2, l2); split1(v.w, h3, l3);
    __nv_bfloat162* hp = (__nv_bfloat162*)(hi + (size_t)i*4);
    __nv_bfloat162* lp = (__nv_bfloat162*)(lo + (size_t)i*4);
    hp[0] = __nv_bfloat162(h0, h1); hp[1] = __nv_bfloat162(h2, h3);
    lp[0] = __nv_bfloat162(l0, l1); lp[1] = __nv_bfloat162(l2, l3);
}

// ============ bf16-split tensor-core GEMM: C[M,N] = A @ B^T (+bias) ========
#define SA 40

__global__ __launch_bounds__(256, 2) void gemm_bf16(
    const __nv_bfloat16* __restrict__ Ah, const __nv_bfloat16* __restrict__ Al,
    const __nv_bfloat16* __restrict__ Bh, const __nv_bfloat16* __restrict__ Bl,
    float* __restrict__ Cp, const float* __restrict__ bias, int N)
{
    __shared__ __align__(16) __nv_bfloat16 sAh[128*SA], sAl[128*SA];
    __shared__ __align__(16) __nv_bfloat16 sBh[128*SA], sBl[128*SA];

    const int tid = threadIdx.x;
    const int wid = tid >> 5, lane = tid & 31;
    const int wm = wid & 3, wn = wid >> 2;
    const int grp = lane >> 2, tq = lane & 3;
    const int bm = blockIdx.y * 128, bn = blockIdx.x * 128;

    float acc[2][8][4] = {};

    for (int kt = 0; kt < KDIM; kt += 32) {
        __syncthreads();
        #pragma unroll
        for (int i = 0; i < 2; i++) {
            int c = tid + i*256;
            int row = c >> 2, kc = c & 3;
            size_t goA = (size_t)(bm + row) * KDIM + kt + kc*8;
            size_t goB = (size_t)(bn + row) * KDIM + kt + kc*8;
            int so = row * SA + kc * 8;
            *(uint4*)&sAh[so] = *(const uint4*)(Ah + goA);
            *(uint4*)&sAl[so] = *(const uint4*)(Al + goA);
            *(uint4*)&sBh[so] = *(const uint4*)(Bh + goB);
            *(uint4*)&sBl[so] = *(const uint4*)(Bl + goB);
        }
        __syncthreads();

        #pragma unroll
        for (int ks = 0; ks < 32; ks += 16) {
            u32 ah[8], al[8];
            #pragma unroll
            for (int mt = 0; mt < 2; mt++) {
                int r0 = (wm*32 + mt*16 + grp) * SA + ks + 2*tq;
                int r1 = r0 + 8*SA;
                ah[mt*4+0] = *(const u32*)&sAh[r0];
                ah[mt*4+1] = *(const u32*)&sAh[r1];
                ah[mt*4+2] = *(const u32*)&sAh[r0 + 8];
                ah[mt*4+3] = *(const u32*)&sAh[r1 + 8];
                al[mt*4+0] = *(const u32*)&sAl[r0];
                al[mt*4+1] = *(const u32*)&sAl[r1];
                al[mt*4+2] = *(const u32*)&sAl[r0 + 8];
                al[mt*4+3] = *(const u32*)&sAl[r1 + 8];
            }
            #pragma unroll
            for (int nt = 0; nt < 8; nt++) {
                int b0 = (wn*64 + nt*8 + grp) * SA + ks + 2*tq;
                u32 bh[2], bl[2];
                bh[0] = *(const u32*)&sBh[b0];
                bh[1] = *(const u32*)&sBh[b0 + 8];
                bl[0] = *(const u32*)&sBl[b0];
                bl[1] = *(const u32*)&sBl[b0 + 8];
                mma_bf16(acc[0][nt], ah,   bh);
                mma_bf16(acc[1][nt], ah+4, bh);
                mma_bf16(acc[0][nt], ah,   bl);
                mma_bf16(acc[1][nt], ah+4, bl);
                mma_bf16(acc[0][nt], al,   bh);
                mma_bf16(acc[1][nt], al+4, bh);
            }
        }
    }

    #pragma unroll
    for (int mt = 0; mt < 2; mt++) {
        int row0 = bm + wm*32 + mt*16 + grp;
        #pragma unroll
        for (int nt = 0; nt < 8; nt++) {
            int col = bn + wn*64 + nt*8 + 2*tq;
            float b0 = 0.f, b1 = 0.f;
            if (bias) { b0 = bias[col]; b1 = bias[col+1]; }
            float2 v0 = make_float2(acc[mt][nt][0] + b0, acc[mt][nt][1] + b1);
            float2 v1 = make_float2(acc[mt][nt][2] + b0, acc[mt][nt][3] + b1);
            *(float2*)(Cp + (size_t)row0       * N + col) = v0;
            *(float2*)(Cp + (size_t)(row0 + 8) * N + col) = v1;
        }
    }
}

// ------------- x path: RMSNorm + RoPE, emit split bf16 q/k/v ---------------
__global__ __launch_bounds__(256) void post_x(
    const float* __restrict__ pos,
    const float* __restrict__ qw, const float* __restrict__ kw)
{
    int wid  = blockIdx.x * 8 + (threadIdx.x >> 5);
    int lane = threadIdx.x & 31;
    int n = wid >> 4;
    int h = wid & 15;
    const float* base = g_qkv + (size_t)n * 3072 + h * 64 + lane * 2;
    float2 q2 = *(const float2*)(base);
    float2 k2 = *(const float2*)(base + 1024);
    float2 v2 = *(const float2*)(base + 2048);
    float sq = q2.x*q2.x + q2.y*q2.y;
    float sk = k2.x*k2.x + k2.y*k2.y;
    #pragma unroll
    for (int off = 16; off > 0; off >>= 1) {
        sq += __shfl_xor_sync(0xffffffffu, sq, off);
        sk += __shfl_xor_sync(0xffffffffu, sk, off);
    }
    float rq = rsqrtf(sq * (1.f/64.f) + 1e-6f);
    float rk = rsqrtf(sk * (1.f/64.f) + 1e-6f);
    float2 wq = *(const float2*)(qw + lane*2);
    float2 wk = *(const float2*)(kw + lane*2);
    float qe = q2.x * rq * wq.x, qo = q2.y * rq * wq.y;
    float ke = k2.x * rk * wk.x, ko = k2.y * rk * wk.y;
    float2 cs = *(const float2*)(pos + (size_t)n*64 + lane*2);
    // rope + scale 0.125 for q
    float qx = (qe*cs.x - qo*cs.y) * 0.125f;
    float qy = (qe*cs.y + qo*cs.x) * 0.125f;
    float kx = ke*cs.x - ko*cs.y;
    float ky = ke*cs.y + ko*cs.x;

    __nv_bfloat16 hh, ll, hh2, ll2;
    size_t qi = ((size_t)h*NQ + n)*64 + lane*2;
    split1(qx, hh, ll); split1(qy, hh2, ll2);
    *(__nv_bfloat162*)&g_qh[qi] = __nv_bfloat162(hh, hh2);
    *(__nv_bfloat162*)&g_ql[qi] = __nv_bfloat162(ll, ll2);
    size_t ki = ((size_t)h*NKV + n)*64 + lane*2;
    split1(kx, hh, ll); split1(ky, hh2, ll2);
    *(__nv_bfloat162*)&g_kh[ki] = __nv_bfloat162(hh, hh2);
    *(__nv_bfloat162*)&g_kl[ki] = __nv_bfloat162(ll, ll2);
    // v transposed: [h][d][key]
    size_t v0 = ((size_t)h*64 + lane*2) * NKV + n;
    split1(v2.x, hh, ll);
    g_vth[v0] = hh; g_vtl[v0] = ll;
    split1(v2.y, hh, ll);
    g_vth[v0 + NKV] = hh; g_vtl[v0 + NKV] = ll;
}

// ------------- y path: RMSNorm(ky), split k/v at key 2048+ -----------------
__global__ __launch_bounds__(256) void post_y(const float* __restrict__ kw)
{
    int wid  = blockIdx.x * 8 + (threadIdx.x >> 5);
    int lane = threadIdx.x & 31;
    int m = wid >> 4;
    int h = wid & 15;
    const float* base = g_kv + (size_t)m * 2048 + h * 64 + lane * 2;
    float2 k2 = *(const float2*)(base);
    float2 v2 = *(const float2*)(base + 1024);
    float sk = k2.x*k2.x + k2.y*k2.y;
    #pragma unroll
    for (int off = 16; off > 0; off >>= 1)
        sk += __shfl_xor_sync(0xffffffffu, sk, off);
    float rk = rsqrtf(sk * (1.f/64.f) + 1e-6f);
    float2 wk = *(const float2*)(kw + lane*2);
    float kx = k2.x * rk * wk.x, ky = k2.y * rk * wk.y;

    __nv_bfloat16 hh, ll, hh2, ll2;
    size_t ki = ((size_t)h*NKV + 2048 + m)*64 + lane*2;
    split1(kx, hh, ll); split1(ky, hh2, ll2);
    *(__nv_bfloat162*)&g_kh[ki] = __nv_bfloat162(hh, hh2);
    *(__nv_bfloat162*)&g_kl[ki] = __nv_bfloat162(ll, ll2);
    size_t v0 = ((size_t)h*64 + lane*2) * NKV + 2048 + m;
    split1(v2.x, hh, ll);
    g_vth[v0] = hh; g_vtl[v0] = ll;
    split1(v2.y, hh, ll);
    g_vth[v0 + NKV] = hh; g_vtl[v0 + NKV] = ll;
}

// ---------------- flash attention via mma.sync -----------------------------
// CTA = (64 q rows, head): 4 warps x 16 rows. K/V tiles of 64 keys in smem.
// S = (Qh+Ql)(Kh+Kl)^T via 3 MMAs; P kept in registers (C->A frag identity);
// O += (Ph+Pl)(Vh+Vl) via 3 MMAs. fp32 online softmax.
#define FS 72   // smem tile row stride (bf16 elems): 144B, 16B-aligned slots

__global__ __launch_bounds__(128) void flash_mma()
{
    __shared__ __align__(16) __nv_bfloat16 sKh[64*FS], sKl[64*FS];
    __shared__ __align__(16) __nv_bfloat16 sVh[64*FS], sVl[64*FS];
    const int h  = blockIdx.y;
    const int qt = blockIdx.x;
    const int tid = threadIdx.x;
    const int wid = tid >> 5, lane = tid & 31;
    const int gid = lane >> 2, tq = lane & 3;
    const int qrow = qt*64 + wid*16 + gid;

    // Q fragments (hi/lo), resident for whole kernel
    u32 aqh[16], aql[16];
    #pragma unroll
    for (int ks = 0; ks < 4; ks++) {
        size_t b = ((size_t)h*NQ + qrow)*64 + ks*16 + 2*tq;
        aqh[ks*4+0] = *(const u32*)&g_qh[b];
        aqh[ks*4+1] = *(const u32*)&g_qh[b + 8*64];
        aqh[ks*4+2] = *(const u32*)&g_qh[b + 8];
        aqh[ks*4+3] = *(const u32*)&g_qh[b + 8*64 + 8];
        aql[ks*4+0] = *(const u32*)&g_ql[b];
        aql[ks*4+1] = *(const u32*)&g_ql[b + 8*64];
        aql[ks*4+2] = *(const u32*)&g_ql[b + 8];
        aql[ks*4+3] = *(const u32*)&g_ql[b + 8*64 + 8];
    }

    float oa[8][4] = {};
    float m0 = -INFINITY, m1 = -INFINITY, l0 = 0.f, l1 = 0.f;

    for (int kt = 0; kt < NKV; kt += 64) {
        __syncthreads();
        {   // cooperative tile load: 128 threads, 64 rows x 2 half-rows
            int row = tid >> 1, hf = tid & 1;
            const __nv_bfloat16* gkh = g_kh + ((size_t)h*NKV + kt + row)*64 + hf*32;
            const __nv_bfloat16* gkl = g_kl + ((size_t)h*NKV + kt + row)*64 + hf*32;
            const __nv_bfloat16* gvh = g_vth + ((size_t)h*64 + row)*NKV + kt + hf*32;
            const __nv_bfloat16* gvl = g_vtl + ((size_t)h*64 + row)*NKV + kt + hf*32;
            int so = row*FS + hf*32;
            #pragma unroll
            for (int i = 0; i < 4; i++) {
                *(uint4*)&sKh[so + i*8] = *(const uint4*)(gkh + i*8);
                *(uint4*)&sKl[so + i*8] = *(const uint4*)(gkl + i*8);
                *(uint4*)&sVh[so + i*8] = *(const uint4*)(gvh + i*8);
                *(uint4*)&sVl[so + i*8] = *(const uint4*)(gvl + i*8);
            }
        }
        __syncthreads();

        // ---- S = Q K^T (split, 3 MMAs per frag) ----
        float s[8][4] = {};
        #pragma unroll
        for (int ks = 0; ks < 4; ks++) {
            #pragma unroll
            for (int j = 0; j < 8; j++) {
                int ko = (8*j + gid)*FS + ks*16 + 2*tq;
                u32 bh[2], bl[2];
                bh[0] = *(const u32*)&sKh[ko];
                bh[1] = *(const u32*)&sKh[ko + 8];
                bl[0] = *(const u32*)&sKl[ko];
                bl[1] = *(const u32*)&sKl[ko + 8];
                mma_bf16(s[j], &aqh[ks*4], bh);
                mma_bf16(s[j], &aqh[ks*4], bl);
                mma_bf16(s[j], &aql[ks*4], bh);
            }
        }

        // ---- online softmax (rows gid and gid+8) ----
        float mx0 = -INFINITY, mx1 = -INFINITY;
        #pragma unroll
        for (int j = 0; j < 8; j++) {
            mx0 = fmaxf(mx0, fmaxf(s[j][0], s[j][1]));
            mx1 = fmaxf(mx1, fmaxf(s[j][2], s[j][3]));
        }
        mx0 = fmaxf(mx0, __shfl_xor_sync(0xffffffffu, mx0, 1));
        mx0 = fmaxf(mx0, __shfl_xor_sync(0xffffffffu, mx0, 2));
        mx1 = fmaxf(mx1, __shfl_xor_sync(0xffffffffu, mx1, 1));
        mx1 = fmaxf(mx1, __shfl_xor_sync(0xffffffffu, mx1, 2));
        float mn0 = fmaxf(m0, mx0), mn1 = fmaxf(m1, mx1);
        float al0 = __expf(m0 - mn0), al1 = __expf(m1 - mn1);
        m0 = mn0; m1 = mn1;
        float ps0 = 0.f, ps1 = 0.f;
        #pragma unroll
        for (int j = 0; j < 8; j++) {
            s[j][0] = __expf(s[j][0] - mn0);
            s[j][1] = __expf(s[j][1] - mn0);
            s[j][2] = __expf(s[j][2] - mn1);
            s[j][3] = __expf(s[j][3] - mn1);
            ps0 += s[j][0] + s[j][1];
            ps1 += s[j][2] + s[j][3];
        }
        ps0 += __shfl_xor_sync(0xffffffffu, ps0, 1);
        ps0 += __shfl_xor_sync(0xffffffffu, ps0, 2);
        ps1 += __shfl_xor_sync(0xffffffffu, ps1, 1);
        ps1 += __shfl_xor_sync(0xffffffffu, ps1, 2);
        l0 = l0*al0 + ps0;
        l1 = l1*al1 + ps1;
        #pragma unroll
        for (int j = 0; j < 8; j++) {
            oa[j][0] *= al0; oa[j][1] *= al0;
            oa[j][2] *= al1; oa[j][3] *= al1;
        }

        // ---- O += P V (P split in registers; 3 MMAs per frag) ----
        #pragma unroll
        for (int ks = 0; ks < 4; ks++) {
            const float* sa = s[2*ks];
            const float* sb = s[2*ks+1];
            u32 ph[4], pl[4];
            ph[0] = packbf2(sa[0], sa[1]);
            ph[1] = packbf2(sa[2], sa[3]);
            ph[2] = packbf2(sb[0], sb[1]);
            ph[3] = packbf2(sb[2], sb[3]);
            #pragma unroll
            for (int r = 0; r < 4; r++) {
                const float* sv = (r < 2) ? sa : sb;
                int e = (r & 1) * 2;
                float lof = __uint_as_float((ph[r] & 0xffffu) << 16);
                float hif = __uint_as_float(ph[r] & 0xffff0000u);
                pl[r] = packbf2(sv[e] - lof, sv[e+1] - hif);
            }
            #pragma unroll
            for (int j = 0; j < 8; j++) {
                int vo = (8*j + gid)*FS + ks*16 + 2*tq;
                u32 bh[2], bl[2];
                bh[0] = *(const u32*)&sVh[vo];
                bh[1] = *(const u32*)&sVh[vo + 8];
                bl[0] = *(const u32*)&sVl[vo];
                bl[1] = *(const u32*)&sVl[vo + 8];
                mma_bf16(oa[j], ph, bh);
                mma_bf16(oa[j], ph, bl);
                mma_bf16(oa[j], pl, bh);
            }
        }
    }

    // ---- epilogue: normalize, write g_o [n][h*64+d] ----
    float i0 = 1.f / l0, i1 = 1.f / l1;
    #pragma unroll
    for (int j = 0; j < 8; j++) {
        int d = h*64 + 8*j + 2*tq;
        *(float2*)(g_o + (size_t)qrow     * CD + d) =
            make_float2(oa[j][0]*i0, oa[j][1]*i0);
        *(float2*)(g_o + (size_t)(qrow+8) * CD + d) =
            make_float2(oa[j][2]*i1, oa[j][3]*i1);
    }
}

// --------------------------------- launch ----------------------------------
extern "C" void kernel_launch(void* const* d_in, const int* in_sizes, int n_in,
                              void* d_out, int out_size)
{
    (void)in_sizes; (void)n_in; (void)out_size;
    const float* x      = (const float*)d_in[0];
    const float* y      = (const float*)d_in[1];
    const float* pos    = (const float*)d_in[2];
    const float* w_qkv  = (const float*)d_in[3];
    const float* w_kv   = (const float*)d_in[4];
    const float* w_proj = (const float*)d_in[5];
    const float* b_proj = (const float*)d_in[6];
    const float* qw     = (const float*)d_in[7];
    const float* kw     = (const float*)d_in[8];
    float* out = (float*)d_out;

    float *qkv, *kv, *ob;
    cudaGetSymbolAddress((void**)&qkv, g_qkv);
    cudaGetSymbolAddress((void**)&kv,  g_kv);
    cudaGetSymbolAddress((void**)&ob,  g_o);
    __nv_bfloat16 *xh,*xl,*yh,*yl,*wqh,*wql,*wkh,*wkl,*wph,*wpl;
    cudaGetSymbolAddress((void**)&xh, g_xh);  cudaGetSymbolAddress((void**)&xl, g_xl);
    cudaGetSymbolAddress((void**)&yh, g_yh);  cudaGetSymbolAddress((void**)&yl, g_yl);
    cudaGetSymbolAddress((void**)&wqh, g_wqh); cudaGetSymbolAddress((void**)&wql, g_wql);
    cudaGetSymbolAddress((void**)&wkh, g_wkh); cudaGetSymbolAddress((void**)&wkl, g_wkl);
    cudaGetSymbolAddress((void**)&wph, g_wph); cudaGetSymbolAddress((void**)&wpl, g_wpl);

    split_kernel<<<(NQ*CD/4 + 255)/256, 256>>>(x, xh, xl, NQ*CD/4);
    split_kernel<<<(NQ*CD/4 + 255)/256, 256>>>(y, yh, yl, NQ*CD/4);
    split_kernel<<<(3*CD*CD/4 + 255)/256, 256>>>(w_qkv, wqh, wql, 3*CD*CD/4);
    split_kernel<<<(2*CD*CD/4 + 255)/256, 256>>>(w_kv,  wkh, wkl, 2*CD*CD/4);
    split_kernel<<<(CD*CD/4 + 255)/256, 256>>>(w_proj, wph, wpl, CD*CD/4);

    // qkv = x @ Wqkv^T, kv = y @ Wkv^T
    gemm_bf16<<<dim3(3072/128, 2048/128), 256>>>(xh, xl, wqh, wql, qkv, nullptr, 3072);
    gemm_bf16<<<dim3(2048/128, 2048/128), 256>>>(yh, yl, wkh, wkl, kv, nullptr, 2048);
    // norms + rope + split/scatter bf16 operands
    post_x<<<4096, 256>>>(pos, qw, kw);
    post_y<<<4096, 256>>>(kw);
    // attention (tensor cores) -> g_o [n][C]
    flash_mma<<<dim3(NQ/64, H), 128>>>();
    // split o, then out = o @ Wproj^T + b
    split_kernel<<<(NQ*CD/4 + 255)/256, 256>>>(ob, xh, xl, NQ*CD/4);
    gemm_bf16<<<dim3(1024/128, 2048/128), 256>>>(xh, xl, wph, wpl, out, b_proj, 1024);
}

// round 13
// speedup vs baseline: 2.2966x; 1.0763x over previous
#include <cuda_runtime.h>
#include <cuda_bf16.h>
#include <math.h>
#include <stdint.h>

#define H   16
#define HD  64
#define NQ  2048
#define NKV 4096
#define CD  1024
#define KDIM 1024

typedef unsigned long long u64;
typedef unsigned int u32;

// ---------------- cp.async helpers ----------------
__device__ __forceinline__ void cp16(u32 smem_addr, const void* gptr) {
    asm volatile("cp.async.cg.shared.global [%0], [%1], 16;"
                 :: "r"(smem_addr), "l"(gptr));
}
__device__ __forceinline__ void cp_commit() {
    asm volatile("cp.async.commit_group;");
}
template<int N> __device__ __forceinline__ void cp_wait() {
    asm volatile("cp.async.wait_group %0;" :: "n"(N));
}
__device__ __forceinline__ u32 smem_u32(const void* p) {
    return (u32)__cvta_generic_to_shared(p);
}

// ---------------- scratch (device globals: allocation-free) ----------------
__device__ __align__(16) float g_qkv[NQ * 3 * CD];
__device__ __align__(16) float g_kv [NQ * 2 * CD];
__device__ __align__(16) float g_o  [NQ * CD];

// pre-split bf16 attention operands
__device__ __align__(16) __nv_bfloat16 g_qh[H*NQ*HD],  g_ql[H*NQ*HD];   // [h][n][d], 0.125 baked in
__device__ __align__(16) __nv_bfloat16 g_kh[H*NKV*HD], g_kl[H*NKV*HD];  // [h][key][d]
__device__ __align__(16) __nv_bfloat16 g_vth[H*HD*NKV], g_vtl[H*HD*NKV];// [h][d][key]

// bf16 split operand buffers for projection GEMMs
__device__ __align__(16) __nv_bfloat16 g_xh[NQ*CD],  g_xl[NQ*CD];    // x, reused for o
__device__ __align__(16) __nv_bfloat16 g_yh[NQ*CD],  g_yl[NQ*CD];
__device__ __align__(16) __nv_bfloat16 g_wqh[3*CD*CD], g_wql[3*CD*CD];
__device__ __align__(16) __nv_bfloat16 g_wkh[2*CD*CD], g_wkl[2*CD*CD];
__device__ __align__(16) __nv_bfloat16 g_wph[CD*CD],   g_wpl[CD*CD];

// ---------------- helpers --------------------------------------------------
__device__ __forceinline__ void split1(float v, __nv_bfloat16& h, __nv_bfloat16& l) {
    h = __float2bfloat16_rn(v);
    l = __float2bfloat16_rn(v - __bfloat162float(h));
}
__device__ __forceinline__ u32 packbf2(float lo, float hi) {
    u32 r;
    asm("cvt.rn.bf16x2.f32 %0, %1, %2;" : "=r"(r) : "f"(hi), "f"(lo));
    return r;
}
__device__ __forceinline__ void mma_bf16(float* c, const u32* a, const u32* b) {
    asm volatile(
        "mma.sync.aligned.m16n8k16.row.col.f32.bf16.bf16.f32 "
        "{%0,%1,%2,%3}, {%4,%5,%6,%7}, {%8,%9}, {%0,%1,%2,%3};"
        : "+f"(c[0]), "+f"(c[1]), "+f"(c[2]), "+f"(c[3])
        : "r"(a[0]), "r"(a[1]), "r"(a[2]), "r"(a[3]), "r"(b[0]), "r"(b[1]));
}

// ---------------- split: fp32 -> bf16 hi + bf16 lo -------------------------
__global__ __launch_bounds__(256) void split_kernel(
    const float* __restrict__ src, __nv_bfloat16* __restrict__ hi,
    __nv_bfloat16* __restrict__ lo, int n4)
{
    int i = blockIdx.x * 256 + threadIdx.x;
    if (i >= n4) return;
    float4 v = ((const float4*)src)[i];
    __nv_bfloat16 h0, h1, h2, h3, l0, l1, l2, l3;
    split1(v.x, h0, l0); split1(v.y, h1, l1);
    split1(v.z, h2, l2); split1(v.w, h3, l3);
    __nv_bfloat162* hp = (__nv_bfloat162*)(hi + (size_t)i*4);
    __nv_bfloat162* lp = (__nv_bfloat162*)(lo + (size_t)i*4);
    hp[0] = __nv_bfloat162(h0, h1); hp[1] = __nv_bfloat162(h2, h3);
    lp[0] = __nv_bfloat162(l0, l1); lp[1] = __nv_bfloat162(l2, l3);
}

// ============ bf16-split tensor-core GEMM, cp.async double-buffered ========
// 128x128 tile, BK=32, 256 threads (8 warps, 4M x 2N), mma.sync m16n8k16.
#define SA 40                     // smem row stride (bf16): 80B, 16B-aligned
#define G_ARR  (128*SA*2)         // bytes per array per stage = 10240
#define G_STG  (4*G_ARR)          // stage size = 40960
#define G_SMEM (2*G_STG)          // 81920

__global__ __launch_bounds__(256, 2) void gemm_bf16(
    const __nv_bfloat16* __restrict__ Ah, const __nv_bfloat16* __restrict__ Al,
    const __nv_bfloat16* __restrict__ Bh, const __nv_bfloat16* __restrict__ Bl,
    float* __restrict__ Cp, const float* __restrict__ bias, int N)
{
    extern __shared__ __align__(16) char dsm[];
    const int tid = threadIdx.x;
    const int wid = tid >> 5, lane = tid & 31;
    const int wm = wid & 3, wn = wid >> 2;
    const int grp = lane >> 2, tq = lane & 3;
    const int bm = blockIdx.y * 128, bn = blockIdx.x * 128;

    const int lrow = tid >> 2, lkc = tid & 3;        // load mapping (2 rows/thread)
    const u32 sbase = smem_u32(dsm);

    // issue async loads of one 128x32 k-tile (4 arrays) into stage st
    auto load_tile = [&](int kt, int st) {
        #pragma unroll
        for (int i = 0; i < 2; i++) {
            int row = lrow + i*64;
            size_t goA = (size_t)(bm + row) * KDIM + kt + lkc*8;
            size_t goB = (size_t)(bn + row) * KDIM + kt + lkc*8;
            u32 so = sbase + st*G_STG + row*(SA*2) + lkc*16;
            cp16(so,           Ah + goA);
            cp16(so + G_ARR,   Al + goA);
            cp16(so + 2*G_ARR, Bh + goB);
            cp16(so + 3*G_ARR, Bl + goB);
        }
    };

    float acc[2][8][4] = {};

    load_tile(0, 0);
    cp_commit();

    for (int t = 0; t < KDIM/32; t++) {
        int st = t & 1;
        if (t < KDIM/32 - 1) {
            load_tile((t+1)*32, st ^ 1);
            cp_commit();
            cp_wait<1>();
        } else {
            cp_wait<0>();
        }
        __syncthreads();

        const __nv_bfloat16* sAh = (const __nv_bfloat16*)(dsm + st*G_STG);
        const __nv_bfloat16* sAl = (const __nv_bfloat16*)(dsm + st*G_STG + G_ARR);
        const __nv_bfloat16* sBh = (const __nv_bfloat16*)(dsm + st*G_STG + 2*G_ARR);
        const __nv_bfloat16* sBl = (const __nv_bfloat16*)(dsm + st*G_STG + 3*G_ARR);

        #pragma unroll
        for (int ks = 0; ks < 32; ks += 16) {
            u32 ah[8], al[8];
            #pragma unroll
            for (int mt = 0; mt < 2; mt++) {
                int r0 = (wm*32 + mt*16 + grp) * SA + ks + 2*tq;
                int r1 = r0 + 8*SA;
                ah[mt*4+0] = *(const u32*)&sAh[r0];
                ah[mt*4+1] = *(const u32*)&sAh[r1];
                ah[mt*4+2] = *(const u32*)&sAh[r0 + 8];
                ah[mt*4+3] = *(const u32*)&sAh[r1 + 8];
                al[mt*4+0] = *(const u32*)&sAl[r0];
                al[mt*4+1] = *(const u32*)&sAl[r1];
                al[mt*4+2] = *(const u32*)&sAl[r0 + 8];
                al[mt*4+3] = *(const u32*)&sAl[r1 + 8];
            }
            #pragma unroll
            for (int nt = 0; nt < 8; nt++) {
                int b0 = (wn*64 + nt*8 + grp) * SA + ks + 2*tq;
                u32 bh[2], bl[2];
                bh[0] = *(const u32*)&sBh[b0];
                bh[1] = *(const u32*)&sBh[b0 + 8];
                bl[0] = *(const u32*)&sBl[b0];
                bl[1] = *(const u32*)&sBl[b0 + 8];
                mma_bf16(acc[0][nt], ah,   bh);
                mma_bf16(acc[1][nt], ah+4, bh);
                mma_bf16(acc[0][nt], ah,   bl);
                mma_bf16(acc[1][nt], ah+4, bl);
                mma_bf16(acc[0][nt], al,   bh);
                mma_bf16(acc[1][nt], al+4, bh);
            }
        }
        __syncthreads();
    }

    #pragma unroll
    for (int mt = 0; mt < 2; mt++) {
        int row0 = bm + wm*32 + mt*16 + grp;
        #pragma unroll
        for (int nt = 0; nt < 8; nt++) {
            int col = bn + wn*64 + nt*8 + 2*tq;
            float b0 = 0.f, b1 = 0.f;
            if (bias) { b0 = bias[col]; b1 = bias[col+1]; }
            float2 v0 = make_float2(acc[mt][nt][0] + b0, acc[mt][nt][1] + b1);
            float2 v1 = make_float2(acc[mt][nt][2] + b0, acc[mt][nt][3] + b1);
            *(float2*)(Cp + (size_t)row0       * N + col) = v0;
            *(float2*)(Cp + (size_t)(row0 + 8) * N + col) = v1;
        }
    }
}

// ------------- x path: RMSNorm + RoPE, emit split bf16 q/k/v ---------------
__global__ __launch_bounds__(256) void post_x(
    const float* __restrict__ pos,
    const float* __restrict__ qw, const float* __restrict__ kw)
{
    int wid  = blockIdx.x * 8 + (threadIdx.x >> 5);
    int lane = threadIdx.x & 31;
    int n = wid >> 4;
    int h = wid & 15;
    const float* base = g_qkv + (size_t)n * 3072 + h * 64 + lane * 2;
    float2 q2 = *(const float2*)(base);
    float2 k2 = *(const float2*)(base + 1024);
    float2 v2 = *(const float2*)(base + 2048);
    float sq = q2.x*q2.x + q2.y*q2.y;
    float sk = k2.x*k2.x + k2.y*k2.y;
    #pragma unroll
    for (int off = 16; off > 0; off >>= 1) {
        sq += __shfl_xor_sync(0xffffffffu, sq, off);
        sk += __shfl_xor_sync(0xffffffffu, sk, off);
    }
    float rq = rsqrtf(sq * (1.f/64.f) + 1e-6f);
    float rk = rsqrtf(sk * (1.f/64.f) + 1e-6f);
    float2 wq = *(const float2*)(qw + lane*2);
    float2 wk = *(const float2*)(kw + lane*2);
    float qe = q2.x * rq * wq.x, qo = q2.y * rq * wq.y;
    float ke = k2.x * rk * wk.x, ko = k2.y * rk * wk.y;
    float2 cs = *(const float2*)(pos + (size_t)n*64 + lane*2);
    float qx = (qe*cs.x - qo*cs.y) * 0.125f;
    float qy = (qe*cs.y + qo*cs.x) * 0.125f;
    float kx = ke*cs.x - ko*cs.y;
    float ky = ke*cs.y + ko*cs.x;

    __nv_bfloat16 hh, ll, hh2, ll2;
    size_t qi = ((size_t)h*NQ + n)*64 + lane*2;
    split1(qx, hh, ll); split1(qy, hh2, ll2);
    *(__nv_bfloat162*)&g_qh[qi] = __nv_bfloat162(hh, hh2);
    *(__nv_bfloat162*)&g_ql[qi] = __nv_bfloat162(ll, ll2);
    size_t ki = ((size_t)h*NKV + n)*64 + lane*2;
    split1(kx, hh, ll); split1(ky, hh2, ll2);
    *(__nv_bfloat162*)&g_kh[ki] = __nv_bfloat162(hh, hh2);
    *(__nv_bfloat162*)&g_kl[ki] = __nv_bfloat162(ll, ll2);
    size_t v0 = ((size_t)h*64 + lane*2) * NKV + n;
    split1(v2.x, hh, ll);
    g_vth[v0] = hh; g_vtl[v0] = ll;
    split1(v2.y, hh, ll);
    g_vth[v0 + NKV] = hh; g_vtl[v0 + NKV] = ll;
}

// ------------- y path: RMSNorm(ky), split k/v at key 2048+ -----------------
__global__ __launch_bounds__(256) void post_y(const float* __restrict__ kw)
{
    int wid  = blockIdx.x * 8 + (threadIdx.x >> 5);
    int lane = threadIdx.x & 31;
    int m = wid >> 4;
    int h = wid & 15;
    const float* base = g_kv + (size_t)m * 2048 + h * 64 + lane * 2;
    float2 k2 = *(const float2*)(base);
    float2 v2 = *(const float2*)(base + 1024);
    float sk = k2.x*k2.x + k2.y*k2.y;
    #pragma unroll
    for (int off = 16; off > 0; off >>= 1)
        sk += __shfl_xor_sync(0xffffffffu, sk, off);
    float rk = rsqrtf(sk * (1.f/64.f) + 1e-6f);
    float2 wk = *(const float2*)(kw + lane*2);
    float kx = k2.x * rk * wk.x, ky = k2.y * rk * wk.y;

    __nv_bfloat16 hh, ll, hh2, ll2;
    size_t ki = ((size_t)h*NKV + 2048 + m)*64 + lane*2;
    split1(kx, hh, ll); split1(ky, hh2, ll2);
    *(__nv_bfloat162*)&g_kh[ki] = __nv_bfloat162(hh, hh2);
    *(__nv_bfloat162*)&g_kl[ki] = __nv_bfloat162(ll, ll2);
    size_t v0 = ((size_t)h*64 + lane*2) * NKV + 2048 + m;
    split1(v2.x, hh, ll);
    g_vth[v0] = hh; g_vtl[v0] = ll;
    split1(v2.y, hh, ll);
    g_vth[v0 + NKV] = hh; g_vtl[v0 + NKV] = ll;
}

// ---------------- flash attention via mma.sync, cp.async pipelined ---------
#define FS 72                      // smem tile row stride (bf16)
#define F_ARR  (64*FS*2)           // 9216 B per array per stage
#define F_STG  (4*F_ARR)           // 36864
#define F_SMEM (2*F_STG)           // 73728

__global__ __launch_bounds__(128) void flash_mma()
{
    extern __shared__ __align__(16) char dsm[];
    const int h  = blockIdx.y;
    const int qt = blockIdx.x;
    const int tid = threadIdx.x;
    const int wid = tid >> 5, lane = tid & 31;
    const int gid = lane >> 2, tq = lane & 3;
    const int qrow = qt*64 + wid*16 + gid;
    const u32 sbase = smem_u32(dsm);

    const int lrow = tid >> 1, lhf = tid & 1;   // tile-load mapping

    auto load_tile = [&](int kt, int st) {
        const __nv_bfloat16* gkh = g_kh + ((size_t)h*NKV + kt + lrow)*64 + lhf*32;
        const __nv_bfloat16* gkl = g_kl + ((size_t)h*NKV + kt + lrow)*64 + lhf*32;
        const __nv_bfloat16* gvh = g_vth + ((size_t)h*64 + lrow)*NKV + kt + lhf*32;
        const __nv_bfloat16* gvl = g_vtl + ((size_t)h*64 + lrow)*NKV + kt + lhf*32;
        u32 so = sbase + st*F_STG + lrow*(FS*2) + lhf*64;
        #pragma unroll
        for (int i = 0; i < 4; i++) {
            cp16(so + i*16,            gkh + i*8);
            cp16(so + i*16 + F_ARR,    gkl + i*8);
            cp16(so + i*16 + 2*F_ARR,  gvh + i*8);
            cp16(so + i*16 + 3*F_ARR,  gvl + i*8);
        }
    };

    // Q fragments (hi/lo), resident for whole kernel
    u32 aqh[16], aql[16];
    #pragma unroll
    for (int ks = 0; ks < 4; ks++) {
        size_t b = ((size_t)h*NQ + qrow)*64 + ks*16 + 2*tq;
        aqh[ks*4+0] = *(const u32*)&g_qh[b];
        aqh[ks*4+1] = *(const u32*)&g_qh[b + 8*64];
        aqh[ks*4+2] = *(const u32*)&g_qh[b + 8];
        aqh[ks*4+3] = *(const u32*)&g_qh[b + 8*64 + 8];
        aql[ks*4+0] = *(const u32*)&g_ql[b];
        aql[ks*4+1] = *(const u32*)&g_ql[b + 8*64];
        aql[ks*4+2] = *(const u32*)&g_ql[b + 8];
        aql[ks*4+3] = *(const u32*)&g_ql[b + 8*64 + 8];
    }

    float oa[8][4] = {};
    float m0 = -INFINITY, m1 = -INFINITY, l0 = 0.f, l1 = 0.f;

    load_tile(0, 0);
    cp_commit();

    for (int t = 0; t < NKV/64; t++) {
        int st = t & 1;
        if (t < NKV/64 - 1) {
            load_tile((t+1)*64, st ^ 1);
            cp_commit();
            cp_wait<1>();
        } else {
            cp_wait<0>();
        }
        __syncthreads();

        const __nv_bfloat16* sKh = (const __nv_bfloat16*)(dsm + st*F_STG);
        const __nv_bfloat16* sKl = (const __nv_bfloat16*)(dsm + st*F_STG + F_ARR);
        const __nv_bfloat16* sVh = (const __nv_bfloat16*)(dsm + st*F_STG + 2*F_ARR);
        const __nv_bfloat16* sVl = (const __nv_bfloat16*)(dsm + st*F_STG + 3*F_ARR);

        // ---- S = Q K^T ----
        float s[8][4] = {};
        #pragma unroll
        for (int ks = 0; ks < 4; ks++) {
            #pragma unroll
            for (int j = 0; j < 8; j++) {
                int ko = (8*j + gid)*FS + ks*16 + 2*tq;
                u32 bh[2], bl[2];
                bh[0] = *(const u32*)&sKh[ko];
                bh[1] = *(const u32*)&sKh[ko + 8];
                bl[0] = *(const u32*)&sKl[ko];
                bl[1] = *(const u32*)&sKl[ko + 8];
                mma_bf16(s[j], &aqh[ks*4], bh);
                mma_bf16(s[j], &aqh[ks*4], bl);
                mma_bf16(s[j], &aql[ks*4], bh);
            }
        }

        // ---- online softmax ----
        float mx0 = -INFINITY, mx1 = -INFINITY;
        #pragma unroll
        for (int j = 0; j < 8; j++) {
            mx0 = fmaxf(mx0, fmaxf(s[j][0], s[j][1]));
            mx1 = fmaxf(mx1, fmaxf(s[j][2], s[j][3]));
        }
        mx0 = fmaxf(mx0, __shfl_xor_sync(0xffffffffu, mx0, 1));
        mx0 = fmaxf(mx0, __shfl_xor_sync(0xffffffffu, mx0, 2));
        mx1 = fmaxf(mx1, __shfl_xor_sync(0xffffffffu, mx1, 1));
        mx1 = fmaxf(mx1, __shfl_xor_sync(0xffffffffu, mx1, 2));
        float mn0 = fmaxf(m0, mx0), mn1 = fmaxf(m1, mx1);
        float al0 = __expf(m0 - mn0), al1 = __expf(m1 - mn1);
        m0 = mn0; m1 = mn1;
        float ps0 = 0.f, ps1 = 0.f;
        #pragma unroll
        for (int j = 0; j < 8; j++) {
            s[j][0] = __expf(s[j][0] - mn0);
            s[j][1] = __expf(s[j][1] - mn0);
            s[j][2] = __expf(s[j][2] - mn1);
            s[j][3] = __expf(s[j][3] - mn1);
            ps0 += s[j][0] + s[j][1];
            ps1 += s[j][2] + s[j][3];
        }
        ps0 += __shfl_xor_sync(0xffffffffu, ps0, 1);
        ps0 += __shfl_xor_sync(0xffffffffu, ps0, 2);
        ps1 += __shfl_xor_sync(0xffffffffu, ps1, 1);
        ps1 += __shfl_xor_sync(0xffffffffu, ps1, 2);
        l0 = l0*al0 + ps0;
        l1 = l1*al1 + ps1;
        #pragma unroll
        for (int j = 0; j < 8; j++) {
            oa[j][0] *= al0; oa[j][1] *= al0;
            oa[j][2] *= al1; oa[j][3] *= al1;
        }

        // ---- O += P V ----
        #pragma unroll
        for (int ks = 0; ks < 4; ks++) {
            const float* sa = s[2*ks];
            const float* sb = s[2*ks+1];
            u32 ph[4], pl[4];
            ph[0] = packbf2(sa[0], sa[1]);
            ph[1] = packbf2(sa[2], sa[3]);
            ph[2] = packbf2(sb[0], sb[1]);
            ph[3] = packbf2(sb[2], sb[3]);
            #pragma unroll
            for (int r = 0; r < 4; r++) {
                const float* sv = (r < 2) ? sa : sb;
                int e = (r & 1) * 2;
                float lof = __uint_as_float((ph[r] & 0xffffu) << 16);
                float hif = __uint_as_float(ph[r] & 0xffff0000u);
                pl[r] = packbf2(sv[e] - lof, sv[e+1] - hif);
            }
            #pragma unroll
            for (int j = 0; j < 8; j++) {
                int vo = (8*j + gid)*FS + ks*16 + 2*tq;
                u32 bh[2], bl[2];
                bh[0] = *(const u32*)&sVh[vo];
                bh[1] = *(const u32*)&sVh[vo + 8];
                bl[0] = *(const u32*)&sVl[vo];
                bl[1] = *(const u32*)&sVl[vo + 8];
                mma_bf16(oa[j], ph, bh);
                mma_bf16(oa[j], ph, bl);
                mma_bf16(oa[j], pl, bh);
            }
        }
        __syncthreads();
    }

    float i0 = 1.f / l0, i1 = 1.f / l1;
    #pragma unroll
    for (int j = 0; j < 8; j++) {
        int d = h*64 + 8*j + 2*tq;
        *(float2*)(g_o + (size_t)qrow     * CD + d) =
            make_float2(oa[j][0]*i0, oa[j][1]*i0);
        *(float2*)(g_o + (size_t)(qrow+8) * CD + d) =
            make_float2(oa[j][2]*i1, oa[j][3]*i1);
    }
}

// --------------------------------- launch ----------------------------------
extern "C" void kernel_launch(void* const* d_in, const int* in_sizes, int n_in,
                              void* d_out, int out_size)
{
    (void)in_sizes; (void)n_in; (void)out_size;
    const float* x      = (const float*)d_in[0];
    const float* y      = (const float*)d_in[1];
    const float* pos    = (const float*)d_in[2];
    const float* w_qkv  = (const float*)d_in[3];
    const float* w_kv   = (const float*)d_in[4];
    const float* w_proj = (const float*)d_in[5];
    const float* b_proj = (const float*)d_in[6];
    const float* qw     = (const float*)d_in[7];
    const float* kw     = (const float*)d_in[8];
    float* out = (float*)d_out;

    float *qkv, *kv, *ob;
    cudaGetSymbolAddress((void**)&qkv, g_qkv);
    cudaGetSymbolAddress((void**)&kv,  g_kv);
    cudaGetSymbolAddress((void**)&ob,  g_o);
    __nv_bfloat16 *xh,*xl,*yh,*yl,*wqh,*wql,*wkh,*wkl,*wph,*wpl;
    cudaGetSymbolAddress((void**)&xh, g_xh);  cudaGetSymbolAddress((void**)&xl, g_xl);
    cudaGetSymbolAddress((void**)&yh, g_yh);  cudaGetSymbolAddress((void**)&yl, g_yl);
    cudaGetSymbolAddress((void**)&wqh, g_wqh); cudaGetSymbolAddress((void**)&wql, g_wql);
    cudaGetSymbolAddress((void**)&wkh, g_wkh); cudaGetSymbolAddress((void**)&wkl, g_wkl);
    cudaGetSymbolAddress((void**)&wph, g_wph); cudaGetSymbolAddress((void**)&wpl, g_wpl);

    cudaFuncSetAttribute(gemm_bf16, cudaFuncAttributeMaxDynamicSharedMemorySize, G_SMEM);
    cudaFuncSetAttribute(flash_mma, cudaFuncAttributeMaxDynamicSharedMemorySize, F_SMEM);

    split_kernel<<<(NQ*CD/4 + 255)/256, 256>>>(x, xh, xl, NQ*CD/4);
    split_kernel<<<(NQ*CD/4 + 255)/256, 256>>>(y, yh, yl, NQ*CD/4);
    split_kernel<<<(3*CD*CD/4 + 255)/256, 256>>>(w_qkv, wqh, wql, 3*CD*CD/4);
    split_kernel<<<(2*CD*CD/4 + 255)/256, 256>>>(w_kv,  wkh, wkl, 2*CD*CD/4);
    split_kernel<<<(CD*CD/4 + 255)/256, 256>>>(w_proj, wph, wpl, CD*CD/4);

    gemm_bf16<<<dim3(3072/128, 2048/128), 256, G_SMEM>>>(xh, xl, wqh, wql, qkv, nullptr, 3072);
    gemm_bf16<<<dim3(2048/128, 2048/128), 256, G_SMEM>>>(yh, yl, wkh, wkl, kv, nullptr, 2048);
    post_x<<<4096, 256>>>(pos, qw, kw);
    post_y<<<4096, 256>>>(kw);
    flash_mma<<<dim3(NQ/64, H), 128, F_SMEM>>>();
    split_kernel<<<(NQ*CD/4 + 255)/256, 256>>>(ob, xh, xl, NQ*CD/4);
    gemm_bf16<<<dim3(1024/128, 2048/128), 256, G_SMEM>>>(xh, xl, wph, wpl, out, b_proj, 1024);
}

// round 14
// speedup vs baseline: 2.2966x; 1.0000x over previous
#include <cuda_runtime.h>
#include <cuda_bf16.h>
#include <math.h>
#include <stdint.h>

#define H   16
#define HD  64
#define NQ  2048
#define NKV 4096
#define CD  1024
#define KDIM 1024

typedef unsigned long long u64;
typedef unsigned int u32;

// ---------------- cp.async helpers ----------------
__device__ __forceinline__ void cp16(u32 smem_addr, const void* gptr) {
    asm volatile("cp.async.cg.shared.global [%0], [%1], 16;"
                 :: "r"(smem_addr), "l"(gptr));
}
__device__ __forceinline__ void cp_commit() {
    asm volatile("cp.async.commit_group;");
}
template<int N> __device__ __forceinline__ void cp_wait() {
    asm volatile("cp.async.wait_group %0;" :: "n"(N));
}
__device__ __forceinline__ u32 smem_u32(const void* p) {
    return (u32)__cvta_generic_to_shared(p);
}

// ---------------- scratch (device globals: allocation-free) ----------------
__device__ __align__(16) float g_qkv[NQ * 3 * CD];
__device__ __align__(16) float g_kv [NQ * 2 * CD];
__device__ __align__(16) float g_o  [NQ * CD];

// pre-split bf16 attention operands
__device__ __align__(16) __nv_bfloat16 g_qh[H*NQ*HD],  g_ql[H*NQ*HD];   // [h][n][d], 0.125 baked in
__device__ __align__(16) __nv_bfloat16 g_kh[H*NKV*HD], g_kl[H*NKV*HD];  // [h][key][d]
__device__ __align__(16) __nv_bfloat16 g_vth[H*HD*NKV], g_vtl[H*HD*NKV];// [h][d][key]

// bf16 split operand buffers for projection GEMMs
__device__ __align__(16) __nv_bfloat16 g_xh[NQ*CD],  g_xl[NQ*CD];    // x, reused for o
__device__ __align__(16) __nv_bfloat16 g_yh[NQ*CD],  g_yl[NQ*CD];
__device__ __align__(16) __nv_bfloat16 g_wqh[3*CD*CD], g_wql[3*CD*CD];
__device__ __align__(16) __nv_bfloat16 g_wkh[2*CD*CD], g_wkl[2*CD*CD];
__device__ __align__(16) __nv_bfloat16 g_wph[CD*CD],   g_wpl[CD*CD];

// ---------------- helpers --------------------------------------------------
__device__ __forceinline__ void split1(float v, __nv_bfloat16& h, __nv_bfloat16& l) {
    h = __float2bfloat16_rn(v);
    l = __float2bfloat16_rn(v - __bfloat162float(h));
}
__device__ __forceinline__ u32 packbf2(float lo, float hi) {
    u32 r;
    asm("cvt.rn.bf16x2.f32 %0, %1, %2;" : "=r"(r) : "f"(hi), "f"(lo));
    return r;
}
__device__ __forceinline__ void mma_bf16(float* c, const u32* a, const u32* b) {
    asm volatile(
        "mma.sync.aligned.m16n8k16.row.col.f32.bf16.bf16.f32 "
        "{%0,%1,%2,%3}, {%4,%5,%6,%7}, {%8,%9}, {%0,%1,%2,%3};"
        : "+f"(c[0]), "+f"(c[1]), "+f"(c[2]), "+f"(c[3])
        : "r"(a[0]), "r"(a[1]), "r"(a[2]), "r"(a[3]), "r"(b[0]), "r"(b[1]));
}

// ---------------- split: fp32 -> bf16 hi + bf16 lo -------------------------
__global__ __launch_bounds__(256) void split_kernel(
    const float* __restrict__ src, __nv_bfloat16* __restrict__ hi,
    __nv_bfloat16* __restrict__ lo, int n4)
{
    int i = blockIdx.x * 256 + threadIdx.x;
    if (i >= n4) return;
    float4 v = ((const float4*)src)[i];
    __nv_bfloat16 h0, h1, h2, h3, l0, l1, l2, l3;
    split1(v.x, h0, l0); split1(v.y, h1, l1);
    split1(v.z, h2, l2); split1(v.w, h3, l3);
    __nv_bfloat162* hp = (__nv_bfloat162*)(hi + (size_t)i*4);
    __nv_bfloat162* lp = (__nv_bfloat162*)(lo + (size_t)i*4);
    hp[0] = __nv_bfloat162(h0, h1); hp[1] = __nv_bfloat162(h2, h3);
    lp[0] = __nv_bfloat162(l0, l1); lp[1] = __nv_bfloat162(l2, l3);
}

// ============ bf16-split tensor-core GEMM, cp.async double-buffered ========
// 128x128 tile, BK=32, 256 threads (8 warps, 4M x 2N), mma.sync m16n8k16.
#define SA 40                     // smem row stride (bf16): 80B, 16B-aligned
#define G_ARR  (128*SA*2)         // bytes per array per stage = 10240
#define G_STG  (4*G_ARR)          // stage size = 40960
#define G_SMEM (2*G_STG)          // 81920

__global__ __launch_bounds__(256, 2) void gemm_bf16(
    const __nv_bfloat16* __restrict__ Ah, const __nv_bfloat16* __restrict__ Al,
    const __nv_bfloat16* __restrict__ Bh, const __nv_bfloat16* __restrict__ Bl,
    float* __restrict__ Cp, const float* __restrict__ bias, int N)
{
    extern __shared__ __align__(16) char dsm[];
    const int tid = threadIdx.x;
    const int wid = tid >> 5, lane = tid & 31;
    const int wm = wid & 3, wn = wid >> 2;
    const int grp = lane >> 2, tq = lane & 3;
    const int bm = blockIdx.y * 128, bn = blockIdx.x * 128;

    const int lrow = tid >> 2, lkc = tid & 3;        // load mapping (2 rows/thread)
    const u32 sbase = smem_u32(dsm);

    // issue async loads of one 128x32 k-tile (4 arrays) into stage st
    auto load_tile = [&](int kt, int st) {
        #pragma unroll
        for (int i = 0; i < 2; i++) {
            int row = lrow + i*64;
            size_t goA = (size_t)(bm + row) * KDIM + kt + lkc*8;
            size_t goB = (size_t)(bn + row) * KDIM + kt + lkc*8;
            u32 so = sbase + st*G_STG + row*(SA*2) + lkc*16;
            cp16(so,           Ah + goA);
            cp16(so + G_ARR,   Al + goA);
            cp16(so + 2*G_ARR, Bh + goB);
            cp16(so + 3*G_ARR, Bl + goB);
        }
    };

    float acc[2][8][4] = {};

    load_tile(0, 0);
    cp_commit();

    for (int t = 0; t < KDIM/32; t++) {
        int st = t & 1;
        if (t < KDIM/32 - 1) {
            load_tile((t+1)*32, st ^ 1);
            cp_commit();
            cp_wait<1>();
        } else {
            cp_wait<0>();
        }
        __syncthreads();

        const __nv_bfloat16* sAh = (const __nv_bfloat16*)(dsm + st*G_STG);
        const __nv_bfloat16* sAl = (const __nv_bfloat16*)(dsm + st*G_STG + G_ARR);
        const __nv_bfloat16* sBh = (const __nv_bfloat16*)(dsm + st*G_STG + 2*G_ARR);
        const __nv_bfloat16* sBl = (const __nv_bfloat16*)(dsm + st*G_STG + 3*G_ARR);

        #pragma unroll
        for (int ks = 0; ks < 32; ks += 16) {
            u32 ah[8], al[8];
            #pragma unroll
            for (int mt = 0; mt < 2; mt++) {
                int r0 = (wm*32 + mt*16 + grp) * SA + ks + 2*tq;
                int r1 = r0 + 8*SA;
                ah[mt*4+0] = *(const u32*)&sAh[r0];
                ah[mt*4+1] = *(const u32*)&sAh[r1];
                ah[mt*4+2] = *(const u32*)&sAh[r0 + 8];
                ah[mt*4+3] = *(const u32*)&sAh[r1 + 8];
                al[mt*4+0] = *(const u32*)&sAl[r0];
                al[mt*4+1] = *(const u32*)&sAl[r1];
                al[mt*4+2] = *(const u32*)&sAl[r0 + 8];
                al[mt*4+3] = *(const u32*)&sAl[r1 + 8];
            }
            #pragma unroll
            for (int nt = 0; nt < 8; nt++) {
                int b0 = (wn*64 + nt*8 + grp) * SA + ks + 2*tq;
                u32 bh[2], bl[2];
                bh[0] = *(const u32*)&sBh[b0];
                bh[1] = *(const u32*)&sBh[b0 + 8];
                bl[0] = *(const u32*)&sBl[b0];
                bl[1] = *(const u32*)&sBl[b0 + 8];
                mma_bf16(acc[0][nt], ah,   bh);
                mma_bf16(acc[1][nt], ah+4, bh);
                mma_bf16(acc[0][nt], ah,   bl);
                mma_bf16(acc[1][nt], ah+4, bl);
                mma_bf16(acc[0][nt], al,   bh);
                mma_bf16(acc[1][nt], al+4, bh);
            }
        }
        __syncthreads();
    }

    #pragma unroll
    for (int mt = 0; mt < 2; mt++) {
        int row0 = bm + wm*32 + mt*16 + grp;
        #pragma unroll
        for (int nt = 0; nt < 8; nt++) {
            int col = bn + wn*64 + nt*8 + 2*tq;
            float b0 = 0.f, b1 = 0.f;
            if (bias) { b0 = bias[col]; b1 = bias[col+1]; }
            float2 v0 = make_float2(acc[mt][nt][0] + b0, acc[mt][nt][1] + b1);
            float2 v1 = make_float2(acc[mt][nt][2] + b0, acc[mt][nt][3] + b1);
            *(float2*)(Cp + (size_t)row0       * N + col) = v0;
            *(float2*)(Cp + (size_t)(row0 + 8) * N + col) = v1;
        }
    }
}

// ------------- x path: RMSNorm + RoPE, emit split bf16 q/k/v ---------------
__global__ __launch_bounds__(256) void post_x(
    const float* __restrict__ pos,
    const float* __restrict__ qw, const float* __restrict__ kw)
{
    int wid  = blockIdx.x * 8 + (threadIdx.x >> 5);
    int lane = threadIdx.x & 31;
    int n = wid >> 4;
    int h = wid & 15;
    const float* base = g_qkv + (size_t)n * 3072 + h * 64 + lane * 2;
    float2 q2 = *(const float2*)(base);
    float2 k2 = *(const float2*)(base + 1024);
    float2 v2 = *(const float2*)(base + 2048);
    float sq = q2.x*q2.x + q2.y*q2.y;
    float sk = k2.x*k2.x + k2.y*k2.y;
    #pragma unroll
    for (int off = 16; off > 0; off >>= 1) {
        sq += __shfl_xor_sync(0xffffffffu, sq, off);
        sk += __shfl_xor_sync(0xffffffffu, sk, off);
    }
    float rq = rsqrtf(sq * (1.f/64.f) + 1e-6f);
    float rk = rsqrtf(sk * (1.f/64.f) + 1e-6f);
    float2 wq = *(const float2*)(qw + lane*2);
    float2 wk = *(const float2*)(kw + lane*2);
    float qe = q2.x * rq * wq.x, qo = q2.y * rq * wq.y;
    float ke = k2.x * rk * wk.x, ko = k2.y * rk * wk.y;
    float2 cs = *(const float2*)(pos + (size_t)n*64 + lane*2);
    float qx = (qe*cs.x - qo*cs.y) * 0.125f;
    float qy = (qe*cs.y + qo*cs.x) * 0.125f;
    float kx = ke*cs.x - ko*cs.y;
    float ky = ke*cs.y + ko*cs.x;

    __nv_bfloat16 hh, ll, hh2, ll2;
    size_t qi = ((size_t)h*NQ + n)*64 + lane*2;
    split1(qx, hh, ll); split1(qy, hh2, ll2);
    *(__nv_bfloat162*)&g_qh[qi] = __nv_bfloat162(hh, hh2);
    *(__nv_bfloat162*)&g_ql[qi] = __nv_bfloat162(ll, ll2);
    size_t ki = ((size_t)h*NKV + n)*64 + lane*2;
    split1(kx, hh, ll); split1(ky, hh2, ll2);
    *(__nv_bfloat162*)&g_kh[ki] = __nv_bfloat162(hh, hh2);
    *(__nv_bfloat162*)&g_kl[ki] = __nv_bfloat162(ll, ll2);
    size_t v0 = ((size_t)h*64 + lane*2) * NKV + n;
    split1(v2.x, hh, ll);
    g_vth[v0] = hh; g_vtl[v0] = ll;
    split1(v2.y, hh, ll);
    g_vth[v0 + NKV] = hh; g_vtl[v0 + NKV] = ll;
}

// ------------- y path: RMSNorm(ky), split k/v at key 2048+ -----------------
__global__ __launch_bounds__(256) void post_y(const float* __restrict__ kw)
{
    int wid  = blockIdx.x * 8 + (threadIdx.x >> 5);
    int lane = threadIdx.x & 31;
    int m = wid >> 4;
    int h = wid & 15;
    const float* base = g_kv + (size_t)m * 2048 + h * 64 + lane * 2;
    float2 k2 = *(const float2*)(base);
    float2 v2 = *(const float2*)(base + 1024);
    float sk = k2.x*k2.x + k2.y*k2.y;
    #pragma unroll
    for (int off = 16; off > 0; off >>= 1)
        sk += __shfl_xor_sync(0xffffffffu, sk, off);
    float rk = rsqrtf(sk * (1.f/64.f) + 1e-6f);
    float2 wk = *(const float2*)(kw + lane*2);
    float kx = k2.x * rk * wk.x, ky = k2.y * rk * wk.y;

    __nv_bfloat16 hh, ll, hh2, ll2;
    size_t ki = ((size_t)h*NKV + 2048 + m)*64 + lane*2;
    split1(kx, hh, ll); split1(ky, hh2, ll2);
    *(__nv_bfloat162*)&g_kh[ki] = __nv_bfloat162(hh, hh2);
    *(__nv_bfloat162*)&g_kl[ki] = __nv_bfloat162(ll, ll2);
    size_t v0 = ((size_t)h*64 + lane*2) * NKV + 2048 + m;
    split1(v2.x, hh, ll);
    g_vth[v0] = hh; g_vtl[v0] = ll;
    split1(v2.y, hh, ll);
    g_vth[v0 + NKV] = hh; g_vtl[v0 + NKV] = ll;
}

// ---------------- flash attention via mma.sync, cp.async pipelined ---------
#define FS 72                      // smem tile row stride (bf16)
#define F_ARR  (64*FS*2)           // 9216 B per array per stage
#define F_STG  (4*F_ARR)           // 36864
#define F_SMEM (2*F_STG)           // 73728

__global__ __launch_bounds__(128) void flash_mma()
{
    extern __shared__ __align__(16) char dsm[];
    const int h  = blockIdx.y;
    const int qt = blockIdx.x;
    const int tid = threadIdx.x;
    const int wid = tid >> 5, lane = tid & 31;
    const int gid = lane >> 2, tq = lane & 3;
    const int qrow = qt*64 + wid*16 + gid;
    const u32 sbase = smem_u32(dsm);

    const int lrow = tid >> 1, lhf = tid & 1;   // tile-load mapping

    auto load_tile = [&](int kt, int st) {
        const __nv_bfloat16* gkh = g_kh + ((size_t)h*NKV + kt + lrow)*64 + lhf*32;
        const __nv_bfloat16* gkl = g_kl + ((size_t)h*NKV + kt + lrow)*64 + lhf*32;
        const __nv_bfloat16* gvh = g_vth + ((size_t)h*64 + lrow)*NKV + kt + lhf*32;
        const __nv_bfloat16* gvl = g_vtl + ((size_t)h*64 + lrow)*NKV + kt + lhf*32;
        u32 so = sbase + st*F_STG + lrow*(FS*2) + lhf*64;
        #pragma unroll
        for (int i = 0; i < 4; i++) {
            cp16(so + i*16,            gkh + i*8);
            cp16(so + i*16 + F_ARR,    gkl + i*8);
            cp16(so + i*16 + 2*F_ARR,  gvh + i*8);
            cp16(so + i*16 + 3*F_ARR,  gvl + i*8);
        }
    };

    // Q fragments (hi/lo), resident for whole kernel
    u32 aqh[16], aql[16];
    #pragma unroll
    for (int ks = 0; ks < 4; ks++) {
        size_t b = ((size_t)h*NQ + qrow)*64 + ks*16 + 2*tq;
        aqh[ks*4+0] = *(const u32*)&g_qh[b];
        aqh[ks*4+1] = *(const u32*)&g_qh[b + 8*64];
        aqh[ks*4+2] = *(const u32*)&g_qh[b + 8];
        aqh[ks*4+3] = *(const u32*)&g_qh[b + 8*64 + 8];
        aql[ks*4+0] = *(const u32*)&g_ql[b];
        aql[ks*4+1] = *(const u32*)&g_ql[b + 8*64];
        aql[ks*4+2] = *(const u32*)&g_ql[b + 8];
        aql[ks*4+3] = *(const u32*)&g_ql[b + 8*64 + 8];
    }

    float oa[8][4] = {};
    float m0 = -INFINITY, m1 = -INFINITY, l0 = 0.f, l1 = 0.f;

    load_tile(0, 0);
    cp_commit();

    for (int t = 0; t < NKV/64; t++) {
        int st = t & 1;
        if (t < NKV/64 - 1) {
            load_tile((t+1)*64, st ^ 1);
            cp_commit();
            cp_wait<1>();
        } else {
            cp_wait<0>();
        }
        __syncthreads();

        const __nv_bfloat16* sKh = (const __nv_bfloat16*)(dsm + st*F_STG);
        const __nv_bfloat16* sKl = (const __nv_bfloat16*)(dsm + st*F_STG + F_ARR);
        const __nv_bfloat16* sVh = (const __nv_bfloat16*)(dsm + st*F_STG + 2*F_ARR);
        const __nv_bfloat16* sVl = (const __nv_bfloat16*)(dsm + st*F_STG + 3*F_ARR);

        // ---- S = Q K^T ----
        float s[8][4] = {};
        #pragma unroll
        for (int ks = 0; ks < 4; ks++) {
            #pragma unroll
            for (int j = 0; j < 8; j++) {
                int ko = (8*j + gid)*FS + ks*16 + 2*tq;
                u32 bh[2], bl[2];
                bh[0] = *(const u32*)&sKh[ko];
                bh[1] = *(const u32*)&sKh[ko + 8];
                bl[0] = *(const u32*)&sKl[ko];
                bl[1] = *(const u32*)&sKl[ko + 8];
                mma_bf16(s[j], &aqh[ks*4], bh);
                mma_bf16(s[j], &aqh[ks*4], bl);
                mma_bf16(s[j], &aql[ks*4], bh);
            }
        }

        // ---- online softmax ----
        float mx0 = -INFINITY, mx1 = -INFINITY;
        #pragma unroll
        for (int j = 0; j < 8; j++) {
            mx0 = fmaxf(mx0, fmaxf(s[j][0], s[j][1]));
            mx1 = fmaxf(mx1, fmaxf(s[j][2], s[j][3]));
        }
        mx0 = fmaxf(mx0, __shfl_xor_sync(0xffffffffu, mx0, 1));
        mx0 = fmaxf(mx0, __shfl_xor_sync(0xffffffffu, mx0, 2));
        mx1 = fmaxf(mx1, __shfl_xor_sync(0xffffffffu, mx1, 1));
        mx1 = fmaxf(mx1, __shfl_xor_sync(0xffffffffu, mx1, 2));
        float mn0 = fmaxf(m0, mx0), mn1 = fmaxf(m1, mx1);
        float al0 = __expf(m0 - mn0), al1 = __expf(m1 - mn1);
        m0 = mn0; m1 = mn1;
        float ps0 = 0.f, ps1 = 0.f;
        #pragma unroll
        for (int j = 0; j < 8; j++) {
            s[j][0] = __expf(s[j][0] - mn0);
            s[j][1] = __expf(s[j][1] - mn0);
            s[j][2] = __expf(s[j][2] - mn1);
            s[j][3] = __expf(s[j][3] - mn1);
            ps0 += s[j][0] + s[j][1];
            ps1 += s[j][2] + s[j][3];
        }
        ps0 += __shfl_xor_sync(0xffffffffu, ps0, 1);
        ps0 += __shfl_xor_sync(0xffffffffu, ps0, 2);
        ps1 += __shfl_xor_sync(0xffffffffu, ps1, 1);
        ps1 += __shfl_xor_sync(0xffffffffu, ps1, 2);
        l0 = l0*al0 + ps0;
        l1 = l1*al1 + ps1;
        #pragma unroll
        for (int j = 0; j < 8; j++) {
            oa[j][0] *= al0; oa[j][1] *= al0;
            oa[j][2] *= al1; oa[j][3] *= al1;
        }

        // ---- O += P V ----
        #pragma unroll
        for (int ks = 0; ks < 4; ks++) {
            const float* sa = s[2*ks];
            const float* sb = s[2*ks+1];
            u32 ph[4], pl[4];
            ph[0] = packbf2(sa[0], sa[1]);
            ph[1] = packbf2(sa[2], sa[3]);
            ph[2] = packbf2(sb[0], sb[1]);
            ph[3] = packbf2(sb[2], sb[3]);
            #pragma unroll
            for (int r = 0; r < 4; r++) {
                const float* sv = (r < 2) ? sa : sb;
                int e = (r & 1) * 2;
                float lof = __uint_as_float((ph[r] & 0xffffu) << 16);
                float hif = __uint_as_float(ph[r] & 0xffff0000u);
                pl[r] = packbf2(sv[e] - lof, sv[e+1] - hif);
            }
            #pragma unroll
            for (int j = 0; j < 8; j++) {
                int vo = (8*j + gid)*FS + ks*16 + 2*tq;
                u32 bh[2], bl[2];
                bh[0] = *(const u32*)&sVh[vo];
                bh[1] = *(const u32*)&sVh[vo + 8];
                bl[0] = *(const u32*)&sVl[vo];
                bl[1] = *(const u32*)&sVl[vo + 8];
                mma_bf16(oa[j], ph, bh);
                mma_bf16(oa[j], ph, bl);
                mma_bf16(oa[j], pl, bh);
            }
        }
        __syncthreads();
    }

    float i0 = 1.f / l0, i1 = 1.f / l1;
    #pragma unroll
    for (int j = 0; j < 8; j++) {
        int d = h*64 + 8*j + 2*tq;
        *(float2*)(g_o + (size_t)qrow     * CD + d) =
            make_float2(oa[j][0]*i0, oa[j][1]*i0);
        *(float2*)(g_o + (size_t)(qrow+8) * CD + d) =
            make_float2(oa[j][2]*i1, oa[j][3]*i1);
    }
}

// --------------------------------- launch ----------------------------------
extern "C" void kernel_launch(void* const* d_in, const int* in_sizes, int n_in,
                              void* d_out, int out_size)
{
    (void)in_sizes; (void)n_in; (void)out_size;
    const float* x      = (const float*)d_in[0];
    const float* y      = (const float*)d_in[1];
    const float* pos    = (const float*)d_in[2];
    const float* w_qkv  = (const float*)d_in[3];
    const float* w_kv   = (const float*)d_in[4];
    const float* w_proj = (const float*)d_in[5];
    const float* b_proj = (const float*)d_in[6];
    const float* qw     = (const float*)d_in[7];
    const float* kw     = (const float*)d_in[8];
    float* out = (float*)d_out;

    float *qkv, *kv, *ob;
    cudaGetSymbolAddress((void**)&qkv, g_qkv);
    cudaGetSymbolAddress((void**)&kv,  g_kv);
    cudaGetSymbolAddress((void**)&ob,  g_o);
    __nv_bfloat16 *xh,*xl,*yh,*yl,*wqh,*wql,*wkh,*wkl,*wph,*wpl;
    cudaGetSymbolAddress((void**)&xh, g_xh);  cudaGetSymbolAddress((void**)&xl, g_xl);
    cudaGetSymbolAddress((void**)&yh, g_yh);  cudaGetSymbolAddress((void**)&yl, g_yl);
    cudaGetSymbolAddress((void**)&wqh, g_wqh); cudaGetSymbolAddress((void**)&wql, g_wql);
    cudaGetSymbolAddress((void**)&wkh, g_wkh); cudaGetSymbolAddress((void**)&wkl, g_wkl);
    cudaGetSymbolAddress((void**)&wph, g_wph); cudaGetSymbolAddress((void**)&wpl, g_wpl);

    cudaFuncSetAttribute(gemm_bf16, cudaFuncAttributeMaxDynamicSharedMemorySize, G_SMEM);
    cudaFuncSetAttribute(flash_mma, cudaFuncAttributeMaxDynamicSharedMemorySize, F_SMEM);

    split_kernel<<<(NQ*CD/4 + 255)/256, 256>>>(x, xh, xl, NQ*CD/4);
    split_kernel<<<(NQ*CD/4 + 255)/256, 256>>>(y, yh, yl, NQ*CD/4);
    split_kernel<<<(3*CD*CD/4 + 255)/256, 256>>>(w_qkv, wqh, wql, 3*CD*CD/4);
    split_kernel<<<(2*CD*CD/4 + 255)/256, 256>>>(w_kv,  wkh, wkl, 2*CD*CD/4);
    split_kernel<<<(CD*CD/4 + 255)/256, 256>>>(w_proj, wph, wpl, CD*CD/4);

    gemm_bf16<<<dim3(3072/128, 2048/128), 256, G_SMEM>>>(xh, xl, wqh, wql, qkv, nullptr, 3072);
    gemm_bf16<<<dim3(2048/128, 2048/128), 256, G_SMEM>>>(yh, yl, wkh, wkl, kv, nullptr, 2048);
    post_x<<<4096, 256>>>(pos, qw, kw);
    post_y<<<4096, 256>>>(kw);
    flash_mma<<<dim3(NQ/64, H), 128, F_SMEM>>>();
    split_kernel<<<(NQ*CD/4 + 255)/256, 256>>>(ob, xh, xl, NQ*CD/4);
    gemm_bf16<<<dim3(1024/128, 2048/128), 256, G_SMEM>>>(xh, xl, wph, wpl, out, b_proj, 1024);
}